// round 2
// baseline (speedup 1.0000x reference)
#include <cuda_runtime.h>
#include <math.h>

// Problem constants
#define Bb   8
#define Tt   2048
#define Ee   1024
#define Hh   128
#define MTOT (Bb * Tt)          // 16384
#define SCALE 0.08838834764831845f  // 1/sqrt(128)

// Scratch (device globals; no allocation allowed)
__device__ float g_Q[MTOT * Hh];
__device__ float g_K[MTOT * Hh];
__device__ float g_V[MTOT * Hh];
__device__ float g_S[(size_t)Bb * Tt * Tt];   // 134 MB scores/probs

// ---------------------------------------------------------------------------
// Kernel 1: QKV projection.  out[z] = x @ W[z],  x:[16384,1024], W:[1024,128]
// Tile 128x128x8, 256 threads, 8x8 per thread.
// ---------------------------------------------------------------------------
__global__ __launch_bounds__(256) void qkv_kernel(
    const float* __restrict__ x,
    const float* __restrict__ Wq,
    const float* __restrict__ Wk,
    const float* __restrict__ Wv)
{
    const float* W   = (blockIdx.z == 0) ? Wq : (blockIdx.z == 1) ? Wk : Wv;
    float*       out = (blockIdx.z == 0) ? g_Q : (blockIdx.z == 1) ? g_K : g_V;

    __shared__ float As[8][128];   // [k][m]
    __shared__ float Bs[8][128];   // [k][n]

    const int tid = threadIdx.x;
    const int m0  = blockIdx.x * 128;
    const int ty  = tid >> 4;      // 0..15
    const int tx  = tid & 15;      // 0..15

    const int arow = tid >> 1;           // 0..127
    const int aseg = (tid & 1) * 4;      // 0 or 4
    const int brow = tid >> 5;           // 0..7
    const int bcol = (tid & 31) * 4;     // 0..124

    float acc[8][8];
#pragma unroll
    for (int i = 0; i < 8; i++)
#pragma unroll
        for (int j = 0; j < 8; j++) acc[i][j] = 0.f;

    const float* aptr = x + (size_t)(m0 + arow) * Ee + aseg;

    for (int k0 = 0; k0 < Ee; k0 += 8) {
        float4 av = *(const float4*)(aptr + k0);
        float4 bv = *(const float4*)(W + (size_t)(k0 + brow) * Hh + bcol);
        As[aseg + 0][arow] = av.x;
        As[aseg + 1][arow] = av.y;
        As[aseg + 2][arow] = av.z;
        As[aseg + 3][arow] = av.w;
        *(float4*)&Bs[brow][bcol] = bv;
        __syncthreads();

#pragma unroll
        for (int kk = 0; kk < 8; kk++) {
            float a[8], b[8];
            *(float4*)&a[0] = *(const float4*)&As[kk][ty * 8];
            *(float4*)&a[4] = *(const float4*)&As[kk][ty * 8 + 4];
            *(float4*)&b[0] = *(const float4*)&Bs[kk][tx * 8];
            *(float4*)&b[4] = *(const float4*)&Bs[kk][tx * 8 + 4];
#pragma unroll
            for (int i = 0; i < 8; i++)
#pragma unroll
                for (int j = 0; j < 8; j++)
                    acc[i][j] += a[i] * b[j];
        }
        __syncthreads();
    }

#pragma unroll
    for (int i = 0; i < 8; i++) {
        int row = m0 + ty * 8 + i;
        float4 o0 = make_float4(acc[i][0], acc[i][1], acc[i][2], acc[i][3]);
        float4 o1 = make_float4(acc[i][4], acc[i][5], acc[i][6], acc[i][7]);
        *(float4*)&out[(size_t)row * Hh + tx * 8]     = o0;
        *(float4*)&out[(size_t)row * Hh + tx * 8 + 4] = o1;
    }
}

// ---------------------------------------------------------------------------
// Kernel 2: scores S = scale * Q K^T, causal mask (-inf above diagonal).
// Per batch z. Tile 128(q) x 128(k) x 8(h). Blocks entirely above the
// diagonal exit immediately (never read downstream).
// ---------------------------------------------------------------------------
__global__ __launch_bounds__(256) void scores_kernel()
{
    const int kt = blockIdx.x;      // key tile
    const int qt = blockIdx.y;      // query tile
    if (kt > qt) return;            // fully masked tile
    const int b  = blockIdx.z;

    const int q0 = qt * 128;
    const int k0 = kt * 128;

    __shared__ float As[8][128];    // Q: [h][q]
    __shared__ float Bs[8][128];    // K: [h][k]

    const int tid  = threadIdx.x;
    const int ty   = tid >> 4;
    const int tx   = tid & 15;
    const int lrow = tid >> 1;
    const int lseg = (tid & 1) * 4;

    float acc[8][8];
#pragma unroll
    for (int i = 0; i < 8; i++)
#pragma unroll
        for (int j = 0; j < 8; j++) acc[i][j] = 0.f;

    const float* qptr = g_Q + ((size_t)(b * Tt + q0 + lrow)) * Hh + lseg;
    const float* kptr = g_K + ((size_t)(b * Tt + k0 + lrow)) * Hh + lseg;

    for (int h0 = 0; h0 < Hh; h0 += 8) {
        float4 av = *(const float4*)(qptr + h0);
        float4 bv = *(const float4*)(kptr + h0);
        As[lseg + 0][lrow] = av.x;
        As[lseg + 1][lrow] = av.y;
        As[lseg + 2][lrow] = av.z;
        As[lseg + 3][lrow] = av.w;
        Bs[lseg + 0][lrow] = bv.x;
        Bs[lseg + 1][lrow] = bv.y;
        Bs[lseg + 2][lrow] = bv.z;
        Bs[lseg + 3][lrow] = bv.w;
        __syncthreads();

#pragma unroll
        for (int kk = 0; kk < 8; kk++) {
            float a[8], bb[8];
            *(float4*)&a[0]  = *(const float4*)&As[kk][ty * 8];
            *(float4*)&a[4]  = *(const float4*)&As[kk][ty * 8 + 4];
            *(float4*)&bb[0] = *(const float4*)&Bs[kk][tx * 8];
            *(float4*)&bb[4] = *(const float4*)&Bs[kk][tx * 8 + 4];
#pragma unroll
            for (int i = 0; i < 8; i++)
#pragma unroll
                for (int j = 0; j < 8; j++)
                    acc[i][j] += a[i] * bb[j];
        }
        __syncthreads();
    }

#pragma unroll
    for (int i = 0; i < 8; i++) {
        int qIdx = q0 + ty * 8 + i;
        float v[8];
#pragma unroll
        for (int j = 0; j < 8; j++) {
            int kIdx = k0 + tx * 8 + j;
            v[j] = (kIdx <= qIdx) ? acc[i][j] * SCALE : -INFINITY;
        }
        size_t base = ((size_t)b * Tt + qIdx) * Tt + k0 + tx * 8;
        *(float4*)&g_S[base]     = make_float4(v[0], v[1], v[2], v[3]);
        *(float4*)&g_S[base + 4] = make_float4(v[4], v[5], v[6], v[7]);
    }
}

// ---------------------------------------------------------------------------
// Kernel 3: row softmax over the first n = ceil128(q+1) entries of each row
// (entries beyond n are never read downstream). Per-element guard idx < n
// (fixes R1 bug: rows with n=128 had cnt=0 and were never normalized).
// ---------------------------------------------------------------------------
__global__ __launch_bounds__(256) void softmax_kernel()
{
    const int row = blockIdx.x;                 // 0..16383
    const int q   = row & (Tt - 1);
    const int n   = ((q >> 7) + 1) << 7;        // multiple of 128, >= 128

    float* Srow = g_S + (size_t)row * Tt;
    const int tid = threadIdx.x;

    float v[8];
    float m = -INFINITY;
#pragma unroll
    for (int i = 0; i < 8; i++) {
        int idx = tid + (i << 8);
        if (idx < n) {
            v[i] = Srow[idx];
            m = fmaxf(m, v[i]);
        } else {
            v[i] = -INFINITY;
        }
    }

    __shared__ float smMax[8];
    __shared__ float smSum[8];

    // block max
#pragma unroll
    for (int o = 16; o; o >>= 1) m = fmaxf(m, __shfl_xor_sync(0xFFFFFFFFu, m, o));
    if ((tid & 31) == 0) smMax[tid >> 5] = m;
    __syncthreads();
    m = smMax[0];
#pragma unroll
    for (int w = 1; w < 8; w++) m = fmaxf(m, smMax[w]);

    float s = 0.f;
#pragma unroll
    for (int i = 0; i < 8; i++) {
        int idx = tid + (i << 8);
        if (idx < n) {
            v[i] = __expf(v[i] - m);   // exp(-inf - m) == 0 for masked entries
            s += v[i];
        }
    }
#pragma unroll
    for (int o = 16; o; o >>= 1) s += __shfl_xor_sync(0xFFFFFFFFu, s, o);
    if ((tid & 31) == 0) smSum[tid >> 5] = s;
    __syncthreads();
    s = smSum[0];
#pragma unroll
    for (int w = 1; w < 8; w++) s += smSum[w];

    float inv = 1.f / s;
#pragma unroll
    for (int i = 0; i < 8; i++) {
        int idx = tid + (i << 8);
        if (idx < n)
            Srow[idx] = v[i] * inv;
    }
}

// ---------------------------------------------------------------------------
// Kernel 4: O = P @ V per batch. P:[2048,2048] (zeros above causal boundary
// within the written region), V:[2048,128]. Tile 64(q) x 128(h) x 8(k),
// 256 threads, 4x8 per thread. K-loop clipped to the causal extent.
// ---------------------------------------------------------------------------
__global__ __launch_bounds__(256) void pv_kernel(float* __restrict__ out)
{
    const int b  = blockIdx.z;
    const int q0 = blockIdx.x * 64;
    const int kmax = (((q0 + 63) >> 7) + 1) << 7;   // causal clip, mult of 128

    __shared__ float As[8][64];    // P: [k][q]
    __shared__ float Bs[8][128];   // V: [k][h]

    const int tid = threadIdx.x;
    const int ty  = tid >> 4;      // 0..15 -> rows ty*4
    const int tx  = tid & 15;      // cols tx*8

    const int arow = tid >> 1;          // used when tid < 128: rows 0..63
    const int aseg = (tid & 1) * 4;
    const int brow = tid >> 5;
    const int bcol = (tid & 31) * 4;

    float acc[4][8];
#pragma unroll
    for (int i = 0; i < 4; i++)
#pragma unroll
        for (int j = 0; j < 8; j++) acc[i][j] = 0.f;

    const float* pbase = g_S + ((size_t)b * Tt + q0 + arow) * Tt + aseg;
    const float* vbase = g_V + (size_t)(b * Tt + brow) * Hh + bcol;

    for (int k0 = 0; k0 < kmax; k0 += 8) {
        if (tid < 128) {
            float4 av = *(const float4*)(pbase + k0);
            As[aseg + 0][arow] = av.x;
            As[aseg + 1][arow] = av.y;
            As[aseg + 2][arow] = av.z;
            As[aseg + 3][arow] = av.w;
        }
        float4 bv = *(const float4*)(vbase + (size_t)k0 * Hh);
        *(float4*)&Bs[brow][bcol] = bv;
        __syncthreads();

#pragma unroll
        for (int kk = 0; kk < 8; kk++) {
            float a[4], bb[8];
            *(float4*)&a[0]  = *(const float4*)&As[kk][ty * 4];
            *(float4*)&bb[0] = *(const float4*)&Bs[kk][tx * 8];
            *(float4*)&bb[4] = *(const float4*)&Bs[kk][tx * 8 + 4];
#pragma unroll
            for (int i = 0; i < 4; i++)
#pragma unroll
                for (int j = 0; j < 8; j++)
                    acc[i][j] += a[i] * bb[j];
        }
        __syncthreads();
    }

#pragma unroll
    for (int i = 0; i < 4; i++) {
        int row = b * Tt + q0 + ty * 4 + i;
        float4 o0 = make_float4(acc[i][0], acc[i][1], acc[i][2], acc[i][3]);
        float4 o1 = make_float4(acc[i][4], acc[i][5], acc[i][6], acc[i][7]);
        *(float4*)&out[(size_t)row * Hh + tx * 8]     = o0;
        *(float4*)&out[(size_t)row * Hh + tx * 8 + 4] = o1;
    }
}

// ---------------------------------------------------------------------------
extern "C" void kernel_launch(void* const* d_in, const int* in_sizes, int n_in,
                              void* d_out, int out_size)
{
    const float* x  = (const float*)d_in[0];
    const float* Wq = (const float*)d_in[1];
    const float* Wk = (const float*)d_in[2];
    const float* Wv = (const float*)d_in[3];
    float* out = (float*)d_out;

    qkv_kernel<<<dim3(128, 1, 3), 256>>>(x, Wq, Wk, Wv);
    scores_kernel<<<dim3(16, 16, 8), 256>>>();
    softmax_kernel<<<dim3(Bb * Tt, 1, 1), 256>>>();
    pv_kernel<<<dim3(32, 1, 8), 256>>>(out);
}

// round 3
// speedup vs baseline: 1.0023x; 1.0023x over previous
#include <cuda_runtime.h>
#include <math.h>

// Problem constants
#define Bb   8
#define Tt   2048
#define Ee   1024
#define Hh   128
#define MTOT (Bb * Tt)          // 16384
#define SCALE 0.08838834764831845f  // 1/sqrt(128)

// Scratch (device globals; no allocation allowed)
__device__ float g_Q[MTOT * Hh];
__device__ float g_K[MTOT * Hh];
__device__ float g_V[MTOT * Hh];
__device__ float g_S[(size_t)Bb * Tt * Tt];   // 134 MB scores/probs

// ---------------------------------------------------------------------------
// Kernel 1: QKV projection.  out[z] = x @ W[z],  x:[16384,1024], W:[1024,128]
// Tile 128x128x8, 256 threads, 8x8 per thread.
// ---------------------------------------------------------------------------
__global__ __launch_bounds__(256) void qkv_kernel(
    const float* __restrict__ x,
    const float* __restrict__ Wq,
    const float* __restrict__ Wk,
    const float* __restrict__ Wv)
{
    const float* W   = (blockIdx.z == 0) ? Wq : (blockIdx.z == 1) ? Wk : Wv;
    float*       out = (blockIdx.z == 0) ? g_Q : (blockIdx.z == 1) ? g_K : g_V;

    __shared__ float As[8][128];   // [k][m]
    __shared__ float Bs[8][128];   // [k][n]

    const int tid = threadIdx.x;
    const int m0  = blockIdx.x * 128;
    const int ty  = tid >> 4;      // 0..15
    const int tx  = tid & 15;      // 0..15

    const int arow = tid >> 1;           // 0..127
    const int aseg = (tid & 1) * 4;      // 0 or 4
    const int brow = tid >> 5;           // 0..7
    const int bcol = (tid & 31) * 4;     // 0..124

    float acc[8][8];
#pragma unroll
    for (int i = 0; i < 8; i++)
#pragma unroll
        for (int j = 0; j < 8; j++) acc[i][j] = 0.f;

    const float* aptr = x + (size_t)(m0 + arow) * Ee + aseg;

    for (int k0 = 0; k0 < Ee; k0 += 8) {
        float4 av = *(const float4*)(aptr + k0);
        float4 bv = *(const float4*)(W + (size_t)(k0 + brow) * Hh + bcol);
        As[aseg + 0][arow] = av.x;
        As[aseg + 1][arow] = av.y;
        As[aseg + 2][arow] = av.z;
        As[aseg + 3][arow] = av.w;
        *(float4*)&Bs[brow][bcol] = bv;
        __syncthreads();

#pragma unroll
        for (int kk = 0; kk < 8; kk++) {
            float a[8], b[8];
            *(float4*)&a[0] = *(const float4*)&As[kk][ty * 8];
            *(float4*)&a[4] = *(const float4*)&As[kk][ty * 8 + 4];
            *(float4*)&b[0] = *(const float4*)&Bs[kk][tx * 8];
            *(float4*)&b[4] = *(const float4*)&Bs[kk][tx * 8 + 4];
#pragma unroll
            for (int i = 0; i < 8; i++)
#pragma unroll
                for (int j = 0; j < 8; j++)
                    acc[i][j] += a[i] * b[j];
        }
        __syncthreads();
    }

#pragma unroll
    for (int i = 0; i < 8; i++) {
        int row = m0 + ty * 8 + i;
        float4 o0 = make_float4(acc[i][0], acc[i][1], acc[i][2], acc[i][3]);
        float4 o1 = make_float4(acc[i][4], acc[i][5], acc[i][6], acc[i][7]);
        *(float4*)&out[(size_t)row * Hh + tx * 8]     = o0;
        *(float4*)&out[(size_t)row * Hh + tx * 8 + 4] = o1;
    }
}

// ---------------------------------------------------------------------------
// Kernel 2: scores S = scale * Q K^T, causal mask (-inf above diagonal).
// Per batch z. Tile 128(q) x 128(k) x 8(h). Blocks entirely above the
// diagonal exit immediately (never read downstream).
// ---------------------------------------------------------------------------
__global__ __launch_bounds__(256) void scores_kernel()
{
    const int kt = blockIdx.x;      // key tile
    const int qt = blockIdx.y;      // query tile
    if (kt > qt) return;            // fully masked tile
    const int b  = blockIdx.z;

    const int q0 = qt * 128;
    const int k0 = kt * 128;

    __shared__ float As[8][128];    // Q: [h][q]
    __shared__ float Bs[8][128];    // K: [h][k]

    const int tid  = threadIdx.x;
    const int ty   = tid >> 4;
    const int tx   = tid & 15;
    const int lrow = tid >> 1;
    const int lseg = (tid & 1) * 4;

    float acc[8][8];
#pragma unroll
    for (int i = 0; i < 8; i++)
#pragma unroll
        for (int j = 0; j < 8; j++) acc[i][j] = 0.f;

    const float* qptr = g_Q + ((size_t)(b * Tt + q0 + lrow)) * Hh + lseg;
    const float* kptr = g_K + ((size_t)(b * Tt + k0 + lrow)) * Hh + lseg;

    for (int h0 = 0; h0 < Hh; h0 += 8) {
        float4 av = *(const float4*)(qptr + h0);
        float4 bv = *(const float4*)(kptr + h0);
        As[lseg + 0][lrow] = av.x;
        As[lseg + 1][lrow] = av.y;
        As[lseg + 2][lrow] = av.z;
        As[lseg + 3][lrow] = av.w;
        Bs[lseg + 0][lrow] = bv.x;
        Bs[lseg + 1][lrow] = bv.y;
        Bs[lseg + 2][lrow] = bv.z;
        Bs[lseg + 3][lrow] = bv.w;
        __syncthreads();

#pragma unroll
        for (int kk = 0; kk < 8; kk++) {
            float a[8], bb[8];
            *(float4*)&a[0]  = *(const float4*)&As[kk][ty * 8];
            *(float4*)&a[4]  = *(const float4*)&As[kk][ty * 8 + 4];
            *(float4*)&bb[0] = *(const float4*)&Bs[kk][tx * 8];
            *(float4*)&bb[4] = *(const float4*)&Bs[kk][tx * 8 + 4];
#pragma unroll
            for (int i = 0; i < 8; i++)
#pragma unroll
                for (int j = 0; j < 8; j++)
                    acc[i][j] += a[i] * bb[j];
        }
        __syncthreads();
    }

#pragma unroll
    for (int i = 0; i < 8; i++) {
        int qIdx = q0 + ty * 8 + i;
        float v[8];
#pragma unroll
        for (int j = 0; j < 8; j++) {
            int kIdx = k0 + tx * 8 + j;
            v[j] = (kIdx <= qIdx) ? acc[i][j] * SCALE : -INFINITY;
        }
        size_t base = ((size_t)b * Tt + qIdx) * Tt + k0 + tx * 8;
        *(float4*)&g_S[base]     = make_float4(v[0], v[1], v[2], v[3]);
        *(float4*)&g_S[base + 4] = make_float4(v[4], v[5], v[6], v[7]);
    }
}

// ---------------------------------------------------------------------------
// Kernel 3: row softmax over the first n = ceil128(q+1) entries of each row
// (entries beyond n are never read downstream). Per-element guard idx < n
// (fixes R1 bug: rows with n=128 had cnt=0 and were never normalized).
// ---------------------------------------------------------------------------
__global__ __launch_bounds__(256) void softmax_kernel()
{
    const int row = blockIdx.x;                 // 0..16383
    const int q   = row & (Tt - 1);
    const int n   = ((q >> 7) + 1) << 7;        // multiple of 128, >= 128

    float* Srow = g_S + (size_t)row * Tt;
    const int tid = threadIdx.x;

    float v[8];
    float m = -INFINITY;
#pragma unroll
    for (int i = 0; i < 8; i++) {
        int idx = tid + (i << 8);
        if (idx < n) {
            v[i] = Srow[idx];
            m = fmaxf(m, v[i]);
        } else {
            v[i] = -INFINITY;
        }
    }

    __shared__ float smMax[8];
    __shared__ float smSum[8];

    // block max
#pragma unroll
    for (int o = 16; o; o >>= 1) m = fmaxf(m, __shfl_xor_sync(0xFFFFFFFFu, m, o));
    if ((tid & 31) == 0) smMax[tid >> 5] = m;
    __syncthreads();
    m = smMax[0];
#pragma unroll
    for (int w = 1; w < 8; w++) m = fmaxf(m, smMax[w]);

    float s = 0.f;
#pragma unroll
    for (int i = 0; i < 8; i++) {
        int idx = tid + (i << 8);
        if (idx < n) {
            v[i] = __expf(v[i] - m);   // exp(-inf - m) == 0 for masked entries
            s += v[i];
        }
    }
#pragma unroll
    for (int o = 16; o; o >>= 1) s += __shfl_xor_sync(0xFFFFFFFFu, s, o);
    if ((tid & 31) == 0) smSum[tid >> 5] = s;
    __syncthreads();
    s = smSum[0];
#pragma unroll
    for (int w = 1; w < 8; w++) s += smSum[w];

    float inv = 1.f / s;
#pragma unroll
    for (int i = 0; i < 8; i++) {
        int idx = tid + (i << 8);
        if (idx < n)
            Srow[idx] = v[i] * inv;
    }
}

// ---------------------------------------------------------------------------
// Kernel 4: O = P @ V per batch. P:[2048,2048] (zeros above causal boundary
// within the written region), V:[2048,128]. Tile 64(q) x 128(h) x 8(k),
// 256 threads, 4x8 per thread. K-loop clipped to the causal extent.
// ---------------------------------------------------------------------------
__global__ __launch_bounds__(256) void pv_kernel(float* __restrict__ out)
{
    const int b  = blockIdx.z;
    const int q0 = blockIdx.x * 64;
    const int kmax = (((q0 + 63) >> 7) + 1) << 7;   // causal clip, mult of 128

    __shared__ float As[8][64];    // P: [k][q]
    __shared__ float Bs[8][128];   // V: [k][h]

    const int tid = threadIdx.x;
    const int ty  = tid >> 4;      // 0..15 -> rows ty*4
    const int tx  = tid & 15;      // cols tx*8

    const int arow = tid >> 1;          // used when tid < 128: rows 0..63
    const int aseg = (tid & 1) * 4;
    const int brow = tid >> 5;
    const int bcol = (tid & 31) * 4;

    float acc[4][8];
#pragma unroll
    for (int i = 0; i < 4; i++)
#pragma unroll
        for (int j = 0; j < 8; j++) acc[i][j] = 0.f;

    const float* pbase = g_S + ((size_t)b * Tt + q0 + arow) * Tt + aseg;
    const float* vbase = g_V + (size_t)(b * Tt + brow) * Hh + bcol;

    for (int k0 = 0; k0 < kmax; k0 += 8) {
        if (tid < 128) {
            float4 av = *(const float4*)(pbase + k0);
            As[aseg + 0][arow] = av.x;
            As[aseg + 1][arow] = av.y;
            As[aseg + 2][arow] = av.z;
            As[aseg + 3][arow] = av.w;
        }
        float4 bv = *(const float4*)(vbase + (size_t)k0 * Hh);
        *(float4*)&Bs[brow][bcol] = bv;
        __syncthreads();

#pragma unroll
        for (int kk = 0; kk < 8; kk++) {
            float a[4], bb[8];
            *(float4*)&a[0]  = *(const float4*)&As[kk][ty * 4];
            *(float4*)&bb[0] = *(const float4*)&Bs[kk][tx * 8];
            *(float4*)&bb[4] = *(const float4*)&Bs[kk][tx * 8 + 4];
#pragma unroll
            for (int i = 0; i < 4; i++)
#pragma unroll
                for (int j = 0; j < 8; j++)
                    acc[i][j] += a[i] * bb[j];
        }
        __syncthreads();
    }

#pragma unroll
    for (int i = 0; i < 4; i++) {
        int row = b * Tt + q0 + ty * 4 + i;
        float4 o0 = make_float4(acc[i][0], acc[i][1], acc[i][2], acc[i][3]);
        float4 o1 = make_float4(acc[i][4], acc[i][5], acc[i][6], acc[i][7]);
        *(float4*)&out[(size_t)row * Hh + tx * 8]     = o0;
        *(float4*)&out[(size_t)row * Hh + tx * 8 + 4] = o1;
    }
}

// ---------------------------------------------------------------------------
extern "C" void kernel_launch(void* const* d_in, const int* in_sizes, int n_in,
                              void* d_out, int out_size)
{
    const float* x  = (const float*)d_in[0];
    const float* Wq = (const float*)d_in[1];
    const float* Wk = (const float*)d_in[2];
    const float* Wv = (const float*)d_in[3];
    float* out = (float*)d_out;

    qkv_kernel<<<dim3(128, 1, 3), 256>>>(x, Wq, Wk, Wv);
    scores_kernel<<<dim3(16, 16, 8), 256>>>();
    softmax_kernel<<<dim3(Bb * Tt, 1, 1), 256>>>();
    pv_kernel<<<dim3(32, 1, 8), 256>>>(out);
}

// round 5
// speedup vs baseline: 2.7033x; 2.6973x over previous
#include <cuda_runtime.h>
#include <cuda_bf16.h>
#include <math.h>
#include <cstdint>

#define Bb 8
#define Tt 2048
#define Ee 1024
#define Hh 128
#define MTOT (Bb * Tt)               // 16384
#define SCALE 0.08838834764831845f  // 1/sqrt(128)

#define STRIDE 72                    // bf16 elems per SMEM row (64 data + 8 pad)
#define PLANE  (128 * STRIDE * 2)    // bytes per [128 x 64] bf16 plane = 18432

// ---------------------------------------------------------------------------
// Device scratch (no allocation allowed)
// ---------------------------------------------------------------------------
__device__ __nv_bfloat16 g_Wt_hi[3 * Hh * Ee];   // W^T per z: [128 n][1024 k]
__device__ __nv_bfloat16 g_Wt_lo[3 * Hh * Ee];
__device__ __nv_bfloat16 g_Qhi[MTOT * Hh], g_Qlo[MTOT * Hh];
__device__ __nv_bfloat16 g_Khi[MTOT * Hh], g_Klo[MTOT * Hh];
__device__ __nv_bfloat16 g_Vthi[Hh * MTOT], g_Vtlo[Hh * MTOT];  // [128 h][16384 tok]
__device__ float g_S[(size_t)Bb * Tt * Tt];                     // 134 MB
__device__ __nv_bfloat16 g_Phi[(size_t)MTOT * Tt], g_Plo[(size_t)MTOT * Tt];

// ---------------------------------------------------------------------------
// PTX helpers (all base-sm_103 legal: ldmatrix + mma.sync)
// ---------------------------------------------------------------------------
__device__ __forceinline__ uint32_t smem_u32(const void* p) {
    uint32_t a;
    asm("{ .reg .u64 t; cvta.to.shared.u64 t, %1; cvt.u32.u64 %0, t; }"
        : "=r"(a) : "l"(p));
    return a;
}

__device__ __forceinline__ void ldsm4(uint32_t& r0, uint32_t& r1,
                                      uint32_t& r2, uint32_t& r3, uint32_t addr) {
    asm volatile("ldmatrix.sync.aligned.m8n8.x4.shared.b16 {%0,%1,%2,%3}, [%4];"
                 : "=r"(r0), "=r"(r1), "=r"(r2), "=r"(r3) : "r"(addr));
}

__device__ __forceinline__ void hmma(float* c, const uint32_t* a, const uint32_t* b) {
    asm volatile(
        "mma.sync.aligned.m16n8k16.row.col.f32.bf16.bf16.f32 "
        "{%0,%1,%2,%3}, {%4,%5,%6,%7}, {%8,%9}, {%0,%1,%2,%3};"
        : "+f"(c[0]), "+f"(c[1]), "+f"(c[2]), "+f"(c[3])
        : "r"(a[0]), "r"(a[1]), "r"(a[2]), "r"(a[3]), "r"(b[0]), "r"(b[1]));
}

// ---------------------------------------------------------------------------
// Shared mainloop body: one 64-wide K chunk.
// SMEM: A_hi @ sA, A_lo @ sA+PLANE, B_hi @ sB, B_lo @ sB+PLANE.
// Warp tile: rows wm*64..+63 (4 m-frags), cols wn*32..+31 (4 n-frags).
// 3-term split: Ah*Bh + Ah*Bl + Al*Bh.
// ---------------------------------------------------------------------------
__device__ __forceinline__ void mma_chunk(uint32_t sA, uint32_t sB,
                                          float acc[4][4][4],
                                          int wm, int wn, int lane)
{
    const int aRow = (lane & 7) + ((lane >> 3) & 1) * 8;
    const int aCol = ((lane >> 4) & 1) * 8;
    const int bRow = (lane & 7) + ((lane >> 4) & 1) * 8;
    const int bCol = ((lane >> 3) & 1) * 8;

#pragma unroll
    for (int ks = 0; ks < 4; ks++) {
        uint32_t Ah[4][4], Al[4][4], Bh[2][4], Bl[2][4];
#pragma unroll
        for (int mf = 0; mf < 4; mf++) {
            uint32_t ad = sA + (uint32_t)((wm * 64 + mf * 16 + aRow) * STRIDE
                                          + ks * 16 + aCol) * 2;
            ldsm4(Ah[mf][0], Ah[mf][1], Ah[mf][2], Ah[mf][3], ad);
            ldsm4(Al[mf][0], Al[mf][1], Al[mf][2], Al[mf][3], ad + PLANE);
        }
#pragma unroll
        for (int np = 0; np < 2; np++) {
            uint32_t bd = sB + (uint32_t)((wn * 32 + np * 16 + bRow) * STRIDE
                                          + ks * 16 + bCol) * 2;
            ldsm4(Bh[np][0], Bh[np][1], Bh[np][2], Bh[np][3], bd);
            ldsm4(Bl[np][0], Bl[np][1], Bl[np][2], Bl[np][3], bd + PLANE);
        }
#pragma unroll
        for (int mf = 0; mf < 4; mf++)
#pragma unroll
            for (int nf = 0; nf < 4; nf++) {
                const uint32_t* bh = &Bh[nf >> 1][(nf & 1) * 2];
                const uint32_t* bl = &Bl[nf >> 1][(nf & 1) * 2];
                hmma(acc[mf][nf], Ah[mf], bh);
                hmma(acc[mf][nf], Ah[mf], bl);
                hmma(acc[mf][nf], Al[mf], bh);
            }
    }
}

__device__ __forceinline__ void store_hilo2(__nv_bfloat16* oh, __nv_bfloat16* ol,
                                            size_t off, float c0, float c1) {
    __nv_bfloat162 h = __floats2bfloat162_rn(c0, c1);
    __nv_bfloat162 l = __floats2bfloat162_rn(c0 - __bfloat162float(h.x),
                                             c1 - __bfloat162float(h.y));
    *(__nv_bfloat162*)(oh + off) = h;
    *(__nv_bfloat162*)(ol + off) = l;
}
__device__ __forceinline__ void store_hilo1(__nv_bfloat16* oh, __nv_bfloat16* ol,
                                            size_t off, float c) {
    __nv_bfloat16 h = __float2bfloat16(c);
    oh[off] = h;
    ol[off] = __float2bfloat16(c - __bfloat162float(h));
}

// ---------------------------------------------------------------------------
// Kernel 0: W^T -> bf16 hi/lo planes.  [3][128 n][1024 k]
// ---------------------------------------------------------------------------
__global__ void prep_w(const float* __restrict__ Wq,
                       const float* __restrict__ Wk,
                       const float* __restrict__ Wv)
{
    const int z = blockIdx.y;
    const float* W = (z == 0) ? Wq : (z == 1) ? Wk : Wv;
    const int idx = blockIdx.x * 256 + threadIdx.x;   // 131072 per z
    const int n = idx >> 10, k = idx & 1023;
    float v = W[k * Hh + n];
    __nv_bfloat16 h = __float2bfloat16(v);
    g_Wt_hi[z * Hh * Ee + idx] = h;
    g_Wt_lo[z * Hh * Ee + idx] = __float2bfloat16(v - __bfloat162float(h));
}

// ---------------------------------------------------------------------------
// Kernel 1: QKV projection via HMMA.  grid (128 m-tiles, 3 z).
// A = x [128 x 64] fp32 -> hi/lo bf16; B = W^T [128 n x 64 k] hi/lo.
// z<2 -> Q/K row-major hi/lo; z==2 -> V transposed [h][tok] hi/lo.
// ---------------------------------------------------------------------------
__global__ __launch_bounds__(256) void qkv_hmma(const float* __restrict__ x)
{
    extern __shared__ char smc[];
    const int z  = blockIdx.y;
    const int m0 = blockIdx.x * 128;
    const int tid = threadIdx.x, lane = tid & 31, wid = tid >> 5;
    const int wm = wid >> 2, wn = wid & 3;
    const uint32_t sA = smem_u32(smc);
    const uint32_t sB = sA + 2 * PLANE;

    const __nv_bfloat16* wh = g_Wt_hi + z * Hh * Ee;
    const __nv_bfloat16* wl = g_Wt_lo + z * Hh * Ee;

    float acc[4][4][4] = {};

    for (int k0 = 0; k0 < Ee; k0 += 64) {
        // A: x fp32 tile [128 x 64] -> hi/lo bf16
#pragma unroll
        for (int i = 0; i < 8; i++) {
            int id = tid + i * 256;          // 0..2047
            int r = id >> 4, ch = id & 15;   // col = ch*4
            float4 v = *(const float4*)(x + (size_t)(m0 + r) * Ee + k0 + ch * 4);
            __nv_bfloat162 h0 = __floats2bfloat162_rn(v.x, v.y);
            __nv_bfloat162 h1 = __floats2bfloat162_rn(v.z, v.w);
            __nv_bfloat162 l0 = __floats2bfloat162_rn(v.x - __bfloat162float(h0.x),
                                                      v.y - __bfloat162float(h0.y));
            __nv_bfloat162 l1 = __floats2bfloat162_rn(v.z - __bfloat162float(h1.x),
                                                      v.w - __bfloat162float(h1.y));
            char* p = smc + (r * STRIDE + ch * 4) * 2;
            *(uint2*)p = make_uint2(*(uint32_t*)&h0, *(uint32_t*)&h1);
            *(uint2*)(p + PLANE) = make_uint2(*(uint32_t*)&l0, *(uint32_t*)&l1);
        }
        // B: W^T bf16 tiles hi/lo
#pragma unroll
        for (int i = 0; i < 4; i++) {
            int id = tid + i * 256;          // 0..1023
            int n = id >> 3, ch = id & 7;    // col = ch*8
            char* p = smc + 2 * PLANE + (n * STRIDE + ch * 8) * 2;
            *(float4*)p           = *(const float4*)(wh + (size_t)n * Ee + k0 + ch * 8);
            *(float4*)(p + PLANE) = *(const float4*)(wl + (size_t)n * Ee + k0 + ch * 8);
        }
        __syncthreads();
        mma_chunk(sA, sB, acc, wm, wn, lane);
        __syncthreads();
    }

    const int gid = lane >> 2, tig = lane & 3;
    if (z < 2) {
        __nv_bfloat16* oh = z ? g_Khi : g_Qhi;
        __nv_bfloat16* ol = z ? g_Klo : g_Qlo;
#pragma unroll
        for (int mf = 0; mf < 4; mf++)
#pragma unroll
            for (int nf = 0; nf < 4; nf++) {
                int col = wn * 32 + nf * 8 + tig * 2;
                int r0  = m0 + wm * 64 + mf * 16 + gid;
                store_hilo2(oh, ol, (size_t)r0 * Hh + col,
                            acc[mf][nf][0], acc[mf][nf][1]);
                store_hilo2(oh, ol, (size_t)(r0 + 8) * Hh + col,
                            acc[mf][nf][2], acc[mf][nf][3]);
            }
    } else {
        // V transposed: g_Vt[h][token]
#pragma unroll
        for (int mf = 0; mf < 4; mf++)
#pragma unroll
            for (int nf = 0; nf < 4; nf++) {
                int n  = wn * 32 + nf * 8 + tig * 2;           // h
                int r0 = m0 + wm * 64 + mf * 16 + gid;          // token
                store_hilo1(g_Vthi, g_Vtlo, (size_t)n * MTOT + r0,           acc[mf][nf][0]);
                store_hilo1(g_Vthi, g_Vtlo, (size_t)(n + 1) * MTOT + r0,     acc[mf][nf][1]);
                store_hilo1(g_Vthi, g_Vtlo, (size_t)n * MTOT + r0 + 8,       acc[mf][nf][2]);
                store_hilo1(g_Vthi, g_Vtlo, (size_t)(n + 1) * MTOT + r0 + 8, acc[mf][nf][3]);
            }
    }
}

// ---------------------------------------------------------------------------
// Kernel 2: scores tile  S = scale * Q K^T with causal mask.
// ---------------------------------------------------------------------------
__global__ __launch_bounds__(256) void scores_hmma()
{
    const int kt = blockIdx.x, qt = blockIdx.y, b = blockIdx.z;
    if (kt > qt) return;

    extern __shared__ char smc[];
    const int tid = threadIdx.x, lane = tid & 31, wid = tid >> 5;
    const int wm = wid >> 2, wn = wid & 3;
    const uint32_t sA = smem_u32(smc);
    const uint32_t sB = sA + 2 * PLANE;

    const __nv_bfloat16* qh = g_Qhi + (size_t)(b * Tt + qt * 128) * Hh;
    const __nv_bfloat16* ql = g_Qlo + (size_t)(b * Tt + qt * 128) * Hh;
    const __nv_bfloat16* kh = g_Khi + (size_t)(b * Tt + kt * 128) * Hh;
    const __nv_bfloat16* kl = g_Klo + (size_t)(b * Tt + kt * 128) * Hh;

    float acc[4][4][4] = {};

#pragma unroll
    for (int c = 0; c < 2; c++) {
        const int k0 = c * 64;
#pragma unroll
        for (int i = 0; i < 4; i++) {
            int id = tid + i * 256;
            int r = id >> 3, ch = id & 7;
            char* pa = smc + (r * STRIDE + ch * 8) * 2;
            char* pb = smc + 2 * PLANE + (r * STRIDE + ch * 8) * 2;
            *(float4*)pa           = *(const float4*)(qh + (size_t)r * Hh + k0 + ch * 8);
            *(float4*)(pa + PLANE) = *(const float4*)(ql + (size_t)r * Hh + k0 + ch * 8);
            *(float4*)pb           = *(const float4*)(kh + (size_t)r * Hh + k0 + ch * 8);
            *(float4*)(pb + PLANE) = *(const float4*)(kl + (size_t)r * Hh + k0 + ch * 8);
        }
        __syncthreads();
        mma_chunk(sA, sB, acc, wm, wn, lane);
        __syncthreads();
    }

    const int gid = lane >> 2, tig = lane & 3;
#pragma unroll
    for (int mf = 0; mf < 4; mf++)
#pragma unroll
        for (int nf = 0; nf < 4; nf++) {
            int kcol = kt * 128 + wn * 32 + nf * 8 + tig * 2;
            int q0   = qt * 128 + wm * 64 + mf * 16 + gid;
#pragma unroll
            for (int half = 0; half < 2; half++) {
                int q = q0 + half * 8;
                float2 v;
                v.x = (kcol     <= q) ? acc[mf][nf][half * 2]     * SCALE : -INFINITY;
                v.y = (kcol + 1 <= q) ? acc[mf][nf][half * 2 + 1] * SCALE : -INFINITY;
                *(float2*)&g_S[((size_t)b * Tt + q) * Tt + kcol] = v;
            }
        }
}

// ---------------------------------------------------------------------------
// Kernel 3: row softmax over first n entries; emit P hi/lo bf16 planes.
// ---------------------------------------------------------------------------
__global__ __launch_bounds__(256) void softmax_kernel()
{
    const int row = blockIdx.x;
    const int q   = row & (Tt - 1);
    const int n   = ((q >> 7) + 1) << 7;

    const float* Srow = g_S + (size_t)row * Tt;
    __nv_bfloat16* ph = g_Phi + (size_t)row * Tt;
    __nv_bfloat16* pl = g_Plo + (size_t)row * Tt;
    const int tid = threadIdx.x;

    float v[8];
    float m = -INFINITY;
#pragma unroll
    for (int i = 0; i < 8; i++) {
        int idx = tid + (i << 8);
        v[i] = (idx < n) ? Srow[idx] : -INFINITY;
        m = fmaxf(m, v[i]);
    }

    __shared__ float smMax[8], smSum[8];
#pragma unroll
    for (int o = 16; o; o >>= 1) m = fmaxf(m, __shfl_xor_sync(0xFFFFFFFFu, m, o));
    if ((tid & 31) == 0) smMax[tid >> 5] = m;
    __syncthreads();
    m = smMax[0];
#pragma unroll
    for (int w = 1; w < 8; w++) m = fmaxf(m, smMax[w]);

    float s = 0.f;
#pragma unroll
    for (int i = 0; i < 8; i++) {
        int idx = tid + (i << 8);
        if (idx < n) { v[i] = __expf(v[i] - m); s += v[i]; }
    }
#pragma unroll
    for (int o = 16; o; o >>= 1) s += __shfl_xor_sync(0xFFFFFFFFu, s, o);
    if ((tid & 31) == 0) smSum[tid >> 5] = s;
    __syncthreads();
    s = smSum[0];
#pragma unroll
    for (int w = 1; w < 8; w++) s += smSum[w];

    const float inv = 1.f / s;
#pragma unroll
    for (int i = 0; i < 8; i++) {
        int idx = tid + (i << 8);
        if (idx < n) {
            float p = v[i] * inv;
            __nv_bfloat16 h = __float2bfloat16(p);
            ph[idx] = h;
            pl[idx] = __float2bfloat16(p - __bfloat162float(h));
        }
    }
}

// ---------------------------------------------------------------------------
// Kernel 4: O = P V per q-tile, K clipped to the causal extent.
// A = P[128 q x k], B = V^T[128 h x k].
// ---------------------------------------------------------------------------
__global__ __launch_bounds__(256) void pv_hmma(float* __restrict__ out)
{
    const int qt = blockIdx.x, b = blockIdx.y;
    const int nch = (qt + 1) * 2;     // 64-wide chunks up to causal boundary

    extern __shared__ char smc[];
    const int tid = threadIdx.x, lane = tid & 31, wid = tid >> 5;
    const int wm = wid >> 2, wn = wid & 3;
    const uint32_t sA = smem_u32(smc);
    const uint32_t sB = sA + 2 * PLANE;

    const __nv_bfloat16* ph = g_Phi + (size_t)(b * Tt + qt * 128) * Tt;
    const __nv_bfloat16* pl = g_Plo + (size_t)(b * Tt + qt * 128) * Tt;
    const __nv_bfloat16* vh = g_Vthi + (size_t)b * Tt;   // row h stride MTOT
    const __nv_bfloat16* vl = g_Vtlo + (size_t)b * Tt;

    float acc[4][4][4] = {};

    for (int c = 0; c < nch; c++) {
        const int k0 = c * 64;
#pragma unroll
        for (int i = 0; i < 4; i++) {
            int id = tid + i * 256;
            int r = id >> 3, ch = id & 7;
            char* pa = smc + (r * STRIDE + ch * 8) * 2;
            char* pb = smc + 2 * PLANE + (r * STRIDE + ch * 8) * 2;
            *(float4*)pa           = *(const float4*)(ph + (size_t)r * Tt + k0 + ch * 8);
            *(float4*)(pa + PLANE) = *(const float4*)(pl + (size_t)r * Tt + k0 + ch * 8);
            *(float4*)pb           = *(const float4*)(vh + (size_t)r * MTOT + k0 + ch * 8);
            *(float4*)(pb + PLANE) = *(const float4*)(vl + (size_t)r * MTOT + k0 + ch * 8);
        }
        __syncthreads();
        mma_chunk(sA, sB, acc, wm, wn, lane);
        __syncthreads();
    }

    const int gid = lane >> 2, tig = lane & 3;
#pragma unroll
    for (int mf = 0; mf < 4; mf++)
#pragma unroll
        for (int nf = 0; nf < 4; nf++) {
            int col = wn * 32 + nf * 8 + tig * 2;
            int r0  = b * Tt + qt * 128 + wm * 64 + mf * 16 + gid;
            *(float2*)&out[(size_t)r0 * Hh + col] =
                make_float2(acc[mf][nf][0], acc[mf][nf][1]);
            *(float2*)&out[(size_t)(r0 + 8) * Hh + col] =
                make_float2(acc[mf][nf][2], acc[mf][nf][3]);
        }
}

// ---------------------------------------------------------------------------
extern "C" void kernel_launch(void* const* d_in, const int* in_sizes, int n_in,
                              void* d_out, int out_size)
{
    const float* x  = (const float*)d_in[0];
    const float* Wq = (const float*)d_in[1];
    const float* Wk = (const float*)d_in[2];
    const float* Wv = (const float*)d_in[3];
    float* out = (float*)d_out;

    const int SMEM = 4 * PLANE;   // 73728 bytes
    cudaFuncSetAttribute(qkv_hmma,    cudaFuncAttributeMaxDynamicSharedMemorySize, SMEM);
    cudaFuncSetAttribute(scores_hmma, cudaFuncAttributeMaxDynamicSharedMemorySize, SMEM);
    cudaFuncSetAttribute(pv_hmma,     cudaFuncAttributeMaxDynamicSharedMemorySize, SMEM);

    prep_w<<<dim3(512, 3), 256>>>(Wq, Wk, Wv);
    qkv_hmma<<<dim3(128, 3), 256, SMEM>>>(x);
    scores_hmma<<<dim3(16, 16, 8), 256, SMEM>>>();
    softmax_kernel<<<MTOT, 256>>>();
    pv_hmma<<<dim3(16, 8), 256, SMEM>>>(out);
}

// round 6
// speedup vs baseline: 3.2039x; 1.1852x over previous
#include <cuda_runtime.h>
#include <cuda_bf16.h>
#include <math.h>
#include <cstdint>

#define Bb 8
#define Tt 2048
#define Ee 1024
#define Hh 128
#define MTOT (Bb * Tt)               // 16384
// scale * log2(e): softmax computed in exp2 domain
#define SC2 0.1275174306f

#define STRIDE 72                    // qkv kernel SMEM row stride (64 data + 8 pad)
#define PLANE  (128 * STRIDE * 2)    // 18432 B

#define FSTR 136                     // fused kernel row stride (128 data + 8 pad)
#define FPL  (128 * FSTR * 2)        // 34816 B per [128 x 128] bf16 plane

// ---------------------------------------------------------------------------
// Device scratch
// ---------------------------------------------------------------------------
__device__ __nv_bfloat16 g_Wt_hi[3 * Hh * Ee];   // W^T per z: [128 n][1024 k]
__device__ __nv_bfloat16 g_Wt_lo[3 * Hh * Ee];
__device__ __nv_bfloat16 g_Qhi[MTOT * Hh], g_Qlo[MTOT * Hh];
__device__ __nv_bfloat16 g_Khi[MTOT * Hh], g_Klo[MTOT * Hh];
__device__ __nv_bfloat16 g_Vthi[Hh * MTOT], g_Vtlo[Hh * MTOT];  // [128 h][16384 tok]

// ---------------------------------------------------------------------------
// PTX helpers
// ---------------------------------------------------------------------------
__device__ __forceinline__ uint32_t smem_u32(const void* p) {
    uint32_t a;
    asm("{ .reg .u64 t; cvta.to.shared.u64 t, %1; cvt.u32.u64 %0, t; }"
        : "=r"(a) : "l"(p));
    return a;
}
__device__ __forceinline__ void ldsm4(uint32_t& r0, uint32_t& r1,
                                      uint32_t& r2, uint32_t& r3, uint32_t addr) {
    asm volatile("ldmatrix.sync.aligned.m8n8.x4.shared.b16 {%0,%1,%2,%3}, [%4];"
                 : "=r"(r0), "=r"(r1), "=r"(r2), "=r"(r3) : "r"(addr));
}
__device__ __forceinline__ void hmma(float* c, const uint32_t* a, const uint32_t* b) {
    asm volatile(
        "mma.sync.aligned.m16n8k16.row.col.f32.bf16.bf16.f32 "
        "{%0,%1,%2,%3}, {%4,%5,%6,%7}, {%8,%9}, {%0,%1,%2,%3};"
        : "+f"(c[0]), "+f"(c[1]), "+f"(c[2]), "+f"(c[3])
        : "r"(a[0]), "r"(a[1]), "r"(a[2]), "r"(a[3]), "r"(b[0]), "r"(b[1]));
}
__device__ __forceinline__ void pack_hilo(uint32_t& h, uint32_t& l, float x, float y) {
    __nv_bfloat162 hh = __floats2bfloat162_rn(x, y);
    __nv_bfloat162 ll = __floats2bfloat162_rn(x - __bfloat162float(hh.x),
                                              y - __bfloat162float(hh.y));
    h = *(uint32_t*)&hh;
    l = *(uint32_t*)&ll;
}

// ---------------------------------------------------------------------------
// qkv mainloop chunk (64-wide K), identical to R5 (validated)
// ---------------------------------------------------------------------------
__device__ __forceinline__ void mma_chunk(uint32_t sA, uint32_t sB,
                                          float acc[4][4][4],
                                          int wm, int wn, int lane)
{
    const int aRow = (lane & 7) + ((lane >> 3) & 1) * 8;
    const int aCol = ((lane >> 4) & 1) * 8;
    const int bRow = (lane & 7) + ((lane >> 4) & 1) * 8;
    const int bCol = ((lane >> 3) & 1) * 8;

#pragma unroll
    for (int ks = 0; ks < 4; ks++) {
        uint32_t Ah[4][4], Al[4][4], Bh[2][4], Bl[2][4];
#pragma unroll
        for (int mf = 0; mf < 4; mf++) {
            uint32_t ad = sA + (uint32_t)((wm * 64 + mf * 16 + aRow) * STRIDE
                                          + ks * 16 + aCol) * 2;
            ldsm4(Ah[mf][0], Ah[mf][1], Ah[mf][2], Ah[mf][3], ad);
            ldsm4(Al[mf][0], Al[mf][1], Al[mf][2], Al[mf][3], ad + PLANE);
        }
#pragma unroll
        for (int np = 0; np < 2; np++) {
            uint32_t bd = sB + (uint32_t)((wn * 32 + np * 16 + bRow) * STRIDE
                                          + ks * 16 + bCol) * 2;
            ldsm4(Bh[np][0], Bh[np][1], Bh[np][2], Bh[np][3], bd);
            ldsm4(Bl[np][0], Bl[np][1], Bl[np][2], Bl[np][3], bd + PLANE);
        }
#pragma unroll
        for (int mf = 0; mf < 4; mf++)
#pragma unroll
            for (int nf = 0; nf < 4; nf++) {
                const uint32_t* bh = &Bh[nf >> 1][(nf & 1) * 2];
                const uint32_t* bl = &Bl[nf >> 1][(nf & 1) * 2];
                hmma(acc[mf][nf], Ah[mf], bh);
                hmma(acc[mf][nf], Ah[mf], bl);
                hmma(acc[mf][nf], Al[mf], bh);
            }
    }
}

__device__ __forceinline__ void store_hilo2(__nv_bfloat16* oh, __nv_bfloat16* ol,
                                            size_t off, float c0, float c1) {
    __nv_bfloat162 h = __floats2bfloat162_rn(c0, c1);
    __nv_bfloat162 l = __floats2bfloat162_rn(c0 - __bfloat162float(h.x),
                                             c1 - __bfloat162float(h.y));
    *(__nv_bfloat162*)(oh + off) = h;
    *(__nv_bfloat162*)(ol + off) = l;
}
__device__ __forceinline__ void store_hilo1(__nv_bfloat16* oh, __nv_bfloat16* ol,
                                            size_t off, float c) {
    __nv_bfloat16 h = __float2bfloat16(c);
    oh[off] = h;
    ol[off] = __float2bfloat16(c - __bfloat162float(h));
}

// ---------------------------------------------------------------------------
// Kernel 0: W^T -> bf16 hi/lo planes
// ---------------------------------------------------------------------------
__global__ void prep_w(const float* __restrict__ Wq,
                       const float* __restrict__ Wk,
                       const float* __restrict__ Wv)
{
    const int z = blockIdx.y;
    const float* W = (z == 0) ? Wq : (z == 1) ? Wk : Wv;
    const int idx = blockIdx.x * 256 + threadIdx.x;
    const int n = idx >> 10, k = idx & 1023;
    float v = W[k * Hh + n];
    __nv_bfloat16 h = __float2bfloat16(v);
    g_Wt_hi[z * Hh * Ee + idx] = h;
    g_Wt_lo[z * Hh * Ee + idx] = __float2bfloat16(v - __bfloat162float(h));
}

// ---------------------------------------------------------------------------
// Kernel 1: QKV projection via HMMA (identical to R5, validated)
// ---------------------------------------------------------------------------
__global__ __launch_bounds__(256) void qkv_hmma(const float* __restrict__ x)
{
    extern __shared__ char smc[];
    const int z  = blockIdx.y;
    const int m0 = blockIdx.x * 128;
    const int tid = threadIdx.x, lane = tid & 31, wid = tid >> 5;
    const int wm = wid >> 2, wn = wid & 3;
    const uint32_t sA = smem_u32(smc);
    const uint32_t sB = sA + 2 * PLANE;

    const __nv_bfloat16* wh = g_Wt_hi + z * Hh * Ee;
    const __nv_bfloat16* wl = g_Wt_lo + z * Hh * Ee;

    float acc[4][4][4] = {};

    for (int k0 = 0; k0 < Ee; k0 += 64) {
#pragma unroll
        for (int i = 0; i < 8; i++) {
            int id = tid + i * 256;
            int r = id >> 4, ch = id & 15;
            float4 v = *(const float4*)(x + (size_t)(m0 + r) * Ee + k0 + ch * 4);
            __nv_bfloat162 h0 = __floats2bfloat162_rn(v.x, v.y);
            __nv_bfloat162 h1 = __floats2bfloat162_rn(v.z, v.w);
            __nv_bfloat162 l0 = __floats2bfloat162_rn(v.x - __bfloat162float(h0.x),
                                                      v.y - __bfloat162float(h0.y));
            __nv_bfloat162 l1 = __floats2bfloat162_rn(v.z - __bfloat162float(h1.x),
                                                      v.w - __bfloat162float(h1.y));
            char* p = smc + (r * STRIDE + ch * 4) * 2;
            *(uint2*)p = make_uint2(*(uint32_t*)&h0, *(uint32_t*)&h1);
            *(uint2*)(p + PLANE) = make_uint2(*(uint32_t*)&l0, *(uint32_t*)&l1);
        }
#pragma unroll
        for (int i = 0; i < 4; i++) {
            int id = tid + i * 256;
            int n = id >> 3, ch = id & 7;
            char* p = smc + 2 * PLANE + (n * STRIDE + ch * 8) * 2;
            *(float4*)p           = *(const float4*)(wh + (size_t)n * Ee + k0 + ch * 8);
            *(float4*)(p + PLANE) = *(const float4*)(wl + (size_t)n * Ee + k0 + ch * 8);
        }
        __syncthreads();
        mma_chunk(sA, sB, acc, wm, wn, lane);
        __syncthreads();
    }

    const int gid = lane >> 2, tig = lane & 3;
    if (z < 2) {
        __nv_bfloat16* oh = z ? g_Khi : g_Qhi;
        __nv_bfloat16* ol = z ? g_Klo : g_Qlo;
#pragma unroll
        for (int mf = 0; mf < 4; mf++)
#pragma unroll
            for (int nf = 0; nf < 4; nf++) {
                int col = wn * 32 + nf * 8 + tig * 2;
                int r0  = m0 + wm * 64 + mf * 16 + gid;
                store_hilo2(oh, ol, (size_t)r0 * Hh + col,
                            acc[mf][nf][0], acc[mf][nf][1]);
                store_hilo2(oh, ol, (size_t)(r0 + 8) * Hh + col,
                            acc[mf][nf][2], acc[mf][nf][3]);
            }
    } else {
#pragma unroll
        for (int mf = 0; mf < 4; mf++)
#pragma unroll
            for (int nf = 0; nf < 4; nf++) {
                int n  = wn * 32 + nf * 8 + tig * 2;
                int r0 = m0 + wm * 64 + mf * 16 + gid;
                store_hilo1(g_Vthi, g_Vtlo, (size_t)n * MTOT + r0,           acc[mf][nf][0]);
                store_hilo1(g_Vthi, g_Vtlo, (size_t)(n + 1) * MTOT + r0,     acc[mf][nf][1]);
                store_hilo1(g_Vthi, g_Vtlo, (size_t)n * MTOT + r0 + 8,       acc[mf][nf][2]);
                store_hilo1(g_Vthi, g_Vtlo, (size_t)(n + 1) * MTOT + r0 + 8, acc[mf][nf][3]);
            }
    }
}

// ---------------------------------------------------------------------------
// Kernel 2: fused flash attention.  One CTA = (b, qt).  8 warps, m16 rows
// per warp.  Loop kt = 0..qt: S tile (HMMA 3-term), online softmax in
// registers, PV (HMMA 3-term, P repacked from S C-fragments).
// SMEM planes: Q hi/lo @0, K hi/lo @2FPL, V^T hi/lo @4FPL.  (209 KB)
// ---------------------------------------------------------------------------
__global__ __launch_bounds__(256) void attn_fused(float* __restrict__ out)
{
    const int qt = blockIdx.x, b = blockIdx.y;

    extern __shared__ char smc[];
    const int tid = threadIdx.x, lane = tid & 31, wid = tid >> 5;
    const int gid = lane >> 2, tig = lane & 3;

    const uint32_t sQ = smem_u32(smc);
    const uint32_t sK = sQ + 2 * FPL;
    const uint32_t sV = sQ + 4 * FPL;

    // Q tile resident (hi/lo)
    const int qb = b * Tt + qt * 128;
#pragma unroll
    for (int i = 0; i < 8; i++) {
        int id = tid + i * 256;
        int r = id >> 4, col = (id & 15) * 8;
        char* p = smc + (r * FSTR + col) * 2;
        *(float4*)p         = *(const float4*)(g_Qhi + (size_t)(qb + r) * Hh + col);
        *(float4*)(p + FPL) = *(const float4*)(g_Qlo + (size_t)(qb + r) * Hh + col);
    }

    float Oa[16][4] = {};
    float m0 = -INFINITY, m1 = -INFINITY, l0 = 0.f, l1 = 0.f;

    const int aRow = (lane & 7) + ((lane >> 3) & 1) * 8;
    const int aCol = ((lane >> 4) & 1) * 8;
    const int bRow = (lane & 7) + ((lane >> 4) & 1) * 8;
    const int bCol = ((lane >> 3) & 1) * 8;

    const int r0w = wid * 16 + gid;   // row within q-tile (row1 = r0w+8)

    for (int kt = 0; kt <= qt; kt++) {
        const int kb = b * Tt + kt * 128;
        // load K tile [tok x feat] and V^T tile [h x tok], hi/lo
#pragma unroll
        for (int i = 0; i < 8; i++) {
            int id = tid + i * 256;
            int r = id >> 4, col = (id & 15) * 8;
            char* pk = smc + 2 * FPL + (r * FSTR + col) * 2;
            *(float4*)pk         = *(const float4*)(g_Khi + (size_t)(kb + r) * Hh + col);
            *(float4*)(pk + FPL) = *(const float4*)(g_Klo + (size_t)(kb + r) * Hh + col);
            char* pv = smc + 4 * FPL + (r * FSTR + col) * 2;
            *(float4*)pv         = *(const float4*)(g_Vthi + (size_t)r * MTOT + kb + col);
            *(float4*)(pv + FPL) = *(const float4*)(g_Vtlo + (size_t)r * MTOT + kb + col);
        }
        __syncthreads();

        // ---- S = Q K^T (3-term split), warp rows [wid*16, +16) ----
        float Sa[16][4] = {};
#pragma unroll
        for (int kc = 0; kc < 8; kc++) {
            uint32_t Ah[4], Al[4];
            uint32_t ad = sQ + (uint32_t)((wid * 16 + aRow) * FSTR + kc * 16 + aCol) * 2;
            ldsm4(Ah[0], Ah[1], Ah[2], Ah[3], ad);
            ldsm4(Al[0], Al[1], Al[2], Al[3], ad + FPL);
#pragma unroll
            for (int ng = 0; ng < 8; ng++) {
                uint32_t Bh[4], Bl[4];
                uint32_t bd = sK + (uint32_t)((ng * 16 + bRow) * FSTR + kc * 16 + bCol) * 2;
                ldsm4(Bh[0], Bh[1], Bh[2], Bh[3], bd);
                ldsm4(Bl[0], Bl[1], Bl[2], Bl[3], bd + FPL);
#pragma unroll
                for (int j = 0; j < 2; j++) {
                    hmma(Sa[ng * 2 + j], Ah, &Bh[2 * j]);
                    hmma(Sa[ng * 2 + j], Ah, &Bl[2 * j]);
                    hmma(Sa[ng * 2 + j], Al, &Bh[2 * j]);
                }
            }
        }

        // ---- scale (exp2 domain) + causal mask + online softmax ----
        const bool diag = (kt == qt);
        float bm0 = -INFINITY, bm1 = -INFINITY;
#pragma unroll
        for (int nf = 0; nf < 16; nf++) {
            int c = nf * 8 + tig * 2;
            float v0 = Sa[nf][0] * SC2, v1 = Sa[nf][1] * SC2;
            float v2 = Sa[nf][2] * SC2, v3 = Sa[nf][3] * SC2;
            if (diag) {
                if (c     > r0w)     v0 = -INFINITY;
                if (c + 1 > r0w)     v1 = -INFINITY;
                if (c     > r0w + 8) v2 = -INFINITY;
                if (c + 1 > r0w + 8) v3 = -INFINITY;
            }
            Sa[nf][0] = v0; Sa[nf][1] = v1; Sa[nf][2] = v2; Sa[nf][3] = v3;
            bm0 = fmaxf(bm0, fmaxf(v0, v1));
            bm1 = fmaxf(bm1, fmaxf(v2, v3));
        }
        bm0 = fmaxf(bm0, __shfl_xor_sync(0xFFFFFFFFu, bm0, 1));
        bm0 = fmaxf(bm0, __shfl_xor_sync(0xFFFFFFFFu, bm0, 2));
        bm1 = fmaxf(bm1, __shfl_xor_sync(0xFFFFFFFFu, bm1, 1));
        bm1 = fmaxf(bm1, __shfl_xor_sync(0xFFFFFFFFu, bm1, 2));

        float nm0 = fmaxf(m0, bm0), nm1 = fmaxf(m1, bm1);
        float a0 = exp2f(m0 - nm0), a1 = exp2f(m1 - nm1);
        m0 = nm0; m1 = nm1;

        float s0 = 0.f, s1 = 0.f;
#pragma unroll
        for (int nf = 0; nf < 16; nf++) {
            Sa[nf][0] = exp2f(Sa[nf][0] - nm0);
            Sa[nf][1] = exp2f(Sa[nf][1] - nm0);
            Sa[nf][2] = exp2f(Sa[nf][2] - nm1);
            Sa[nf][3] = exp2f(Sa[nf][3] - nm1);
            s0 += Sa[nf][0] + Sa[nf][1];
            s1 += Sa[nf][2] + Sa[nf][3];
        }
        s0 += __shfl_xor_sync(0xFFFFFFFFu, s0, 1);
        s0 += __shfl_xor_sync(0xFFFFFFFFu, s0, 2);
        s1 += __shfl_xor_sync(0xFFFFFFFFu, s1, 1);
        s1 += __shfl_xor_sync(0xFFFFFFFFu, s1, 2);
        l0 = l0 * a0 + s0;
        l1 = l1 * a1 + s1;

#pragma unroll
        for (int nf = 0; nf < 16; nf++) {
            Oa[nf][0] *= a0; Oa[nf][1] *= a0;
            Oa[nf][2] *= a1; Oa[nf][3] *= a1;
        }

        // ---- O += P V (3-term; P from S fragments) ----
#pragma unroll
        for (int kc = 0; kc < 8; kc++) {
            uint32_t Ph[4], Pl[4];
            pack_hilo(Ph[0], Pl[0], Sa[2 * kc][0],     Sa[2 * kc][1]);
            pack_hilo(Ph[1], Pl[1], Sa[2 * kc][2],     Sa[2 * kc][3]);
            pack_hilo(Ph[2], Pl[2], Sa[2 * kc + 1][0], Sa[2 * kc + 1][1]);
            pack_hilo(Ph[3], Pl[3], Sa[2 * kc + 1][2], Sa[2 * kc + 1][3]);
#pragma unroll
            for (int ng = 0; ng < 8; ng++) {
                uint32_t Vh[4], Vl[4];
                uint32_t bd = sV + (uint32_t)((ng * 16 + bRow) * FSTR + kc * 16 + bCol) * 2;
                ldsm4(Vh[0], Vh[1], Vh[2], Vh[3], bd);
                ldsm4(Vl[0], Vl[1], Vl[2], Vl[3], bd + FPL);
#pragma unroll
                for (int j = 0; j < 2; j++) {
                    hmma(Oa[ng * 2 + j], Ph, &Vh[2 * j]);
                    hmma(Oa[ng * 2 + j], Ph, &Vl[2 * j]);
                    hmma(Oa[ng * 2 + j], Pl, &Vh[2 * j]);
                }
            }
        }
        __syncthreads();
    }

    // ---- epilogue: normalize + store fp32 ----
    const float inv0 = 1.f / l0, inv1 = 1.f / l1;
    const int orow = b * Tt + qt * 128 + wid * 16 + gid;
#pragma unroll
    for (int nf = 0; nf < 16; nf++) {
        int col = nf * 8 + tig * 2;
        *(float2*)&out[(size_t)orow * Hh + col] =
            make_float2(Oa[nf][0] * inv0, Oa[nf][1] * inv0);
        *(float2*)&out[(size_t)(orow + 8) * Hh + col] =
            make_float2(Oa[nf][2] * inv1, Oa[nf][3] * inv1);
    }
}

// ---------------------------------------------------------------------------
extern "C" void kernel_launch(void* const* d_in, const int* in_sizes, int n_in,
                              void* d_out, int out_size)
{
    const float* x  = (const float*)d_in[0];
    const float* Wq = (const float*)d_in[1];
    const float* Wk = (const float*)d_in[2];
    const float* Wv = (const float*)d_in[3];
    float* out = (float*)d_out;

    const int SMEM_QKV  = 4 * PLANE;   // 73728
    const int SMEM_ATTN = 6 * FPL;     // 208896
    cudaFuncSetAttribute(qkv_hmma,   cudaFuncAttributeMaxDynamicSharedMemorySize, SMEM_QKV);
    cudaFuncSetAttribute(attn_fused, cudaFuncAttributeMaxDynamicSharedMemorySize, SMEM_ATTN);

    prep_w<<<dim3(512, 3), 256>>>(Wq, Wk, Wv);
    qkv_hmma<<<dim3(128, 3), 256, SMEM_QKV>>>(x);
    attn_fused<<<dim3(16, 8), 256, SMEM_ATTN>>>(out);
}

// round 7
// speedup vs baseline: 3.9826x; 1.2431x over previous
#include <cuda_runtime.h>
#include <cuda_bf16.h>
#include <math.h>
#include <cstdint>

#define Bb 8
#define Tt 2048
#define Ee 1024
#define Hh 128
#define MTOT (Bb * Tt)               // 16384
// scale * log2(e): softmax computed in exp2 domain
#define SC2 0.1275174306f

#define STRIDE 72                    // qkv kernel SMEM row stride (64 data + 8 pad)
#define PLANE  (128 * STRIDE * 2)    // 18432 B

#define FSTR 136                     // fused kernel row stride (128 data + 8 pad)
#define FPL  (128 * FSTR * 2)        // 34816 B per [128 x 128] bf16 plane

#define NITEMS 40                    // work items per batch (chunked causal tiles)
#define NCTA   (NITEMS * Bb)         // 320

// ---------------------------------------------------------------------------
// Device scratch
// ---------------------------------------------------------------------------
__device__ __nv_bfloat16 g_Wt_hi[3 * Hh * Ee];
__device__ __nv_bfloat16 g_Wt_lo[3 * Hh * Ee];
__device__ __nv_bfloat16 g_Qhi[MTOT * Hh], g_Qlo[MTOT * Hh];
__device__ __nv_bfloat16 g_Khi[MTOT * Hh], g_Klo[MTOT * Hh];
__device__ __nv_bfloat16 g_Vthi[Hh * MTOT], g_Vtlo[Hh * MTOT];  // [128 h][16384 tok]

__device__ float g_Opart[NCTA][128 * 128];   // 21 MB unnormalized partials
__device__ float g_mpart[NCTA][128];
__device__ float g_lpart[NCTA][128];

// Work tables: items sorted by descending nk so big chunks launch first.
__device__ const int WK_QT[NITEMS] = {
    3,4,5,6,7,7,8,8,9,9,10,10,11,11,11,12,12,12,13,13,13,14,14,14,15,15,15,15,
    2,6,10,14,  1,5,9,13,  0,4,8,12};
__device__ const int WK_C0[NITEMS] = {
    0,0,0,0,0,4,0,4,0,4,0,4,0,4,8,0,4,8,0,4,8,0,4,8,0,4,8,12,
    0,4,8,12,  0,4,8,12,  0,4,8,12};
__device__ const int WK_NK[NITEMS] = {
    4,4,4,4,4,4,4,4,4,4,4,4,4,4,4,4,4,4,4,4,4,4,4,4,4,4,4,4,
    3,3,3,3,  2,2,2,2,  1,1,1,1};
// reverse map: (qt) -> its item indices (within batch)
__device__ const int QT_NCH[16] = {1,1,1,1,2,2,2,2,3,3,3,3,4,4,4,4};
__device__ const int QT_ITEMS[16][4] = {
    {36,0,0,0},{32,0,0,0},{28,0,0,0},{0,0,0,0},
    {1,37,0,0},{2,33,0,0},{3,29,0,0},{4,5,0,0},
    {6,7,38,0},{8,9,34,0},{10,11,30,0},{12,13,14,0},
    {15,16,17,39},{18,19,20,35},{21,22,23,31},{24,25,26,27}};

// ---------------------------------------------------------------------------
// PTX helpers
// ---------------------------------------------------------------------------
__device__ __forceinline__ uint32_t smem_u32(const void* p) {
    uint32_t a;
    asm("{ .reg .u64 t; cvta.to.shared.u64 t, %1; cvt.u32.u64 %0, t; }"
        : "=r"(a) : "l"(p));
    return a;
}
__device__ __forceinline__ void ldsm4(uint32_t& r0, uint32_t& r1,
                                      uint32_t& r2, uint32_t& r3, uint32_t addr) {
    asm volatile("ldmatrix.sync.aligned.m8n8.x4.shared.b16 {%0,%1,%2,%3}, [%4];"
                 : "=r"(r0), "=r"(r1), "=r"(r2), "=r"(r3) : "r"(addr));
}
__device__ __forceinline__ void hmma(float* c, const uint32_t* a, const uint32_t* b) {
    asm volatile(
        "mma.sync.aligned.m16n8k16.row.col.f32.bf16.bf16.f32 "
        "{%0,%1,%2,%3}, {%4,%5,%6,%7}, {%8,%9}, {%0,%1,%2,%3};"
        : "+f"(c[0]), "+f"(c[1]), "+f"(c[2]), "+f"(c[3])
        : "r"(a[0]), "r"(a[1]), "r"(a[2]), "r"(a[3]), "r"(b[0]), "r"(b[1]));
}
__device__ __forceinline__ void pack_hilo(uint32_t& h, uint32_t& l, float x, float y) {
    __nv_bfloat162 hh = __floats2bfloat162_rn(x, y);
    __nv_bfloat162 ll = __floats2bfloat162_rn(x - __bfloat162float(hh.x),
                                              y - __bfloat162float(hh.y));
    h = *(uint32_t*)&hh;
    l = *(uint32_t*)&ll;
}

// ---------------------------------------------------------------------------
// qkv mainloop chunk (validated R5)
// ---------------------------------------------------------------------------
__device__ __forceinline__ void mma_chunk(uint32_t sA, uint32_t sB,
                                          float acc[4][4][4],
                                          int wm, int wn, int lane)
{
    const int aRow = (lane & 7) + ((lane >> 3) & 1) * 8;
    const int aCol = ((lane >> 4) & 1) * 8;
    const int bRow = (lane & 7) + ((lane >> 4) & 1) * 8;
    const int bCol = ((lane >> 3) & 1) * 8;

#pragma unroll
    for (int ks = 0; ks < 4; ks++) {
        uint32_t Ah[4][4], Al[4][4], Bh[2][4], Bl[2][4];
#pragma unroll
        for (int mf = 0; mf < 4; mf++) {
            uint32_t ad = sA + (uint32_t)((wm * 64 + mf * 16 + aRow) * STRIDE
                                          + ks * 16 + aCol) * 2;
            ldsm4(Ah[mf][0], Ah[mf][1], Ah[mf][2], Ah[mf][3], ad);
            ldsm4(Al[mf][0], Al[mf][1], Al[mf][2], Al[mf][3], ad + PLANE);
        }
#pragma unroll
        for (int np = 0; np < 2; np++) {
            uint32_t bd = sB + (uint32_t)((wn * 32 + np * 16 + bRow) * STRIDE
                                          + ks * 16 + bCol) * 2;
            ldsm4(Bh[np][0], Bh[np][1], Bh[np][2], Bh[np][3], bd);
            ldsm4(Bl[np][0], Bl[np][1], Bl[np][2], Bl[np][3], bd + PLANE);
        }
#pragma unroll
        for (int mf = 0; mf < 4; mf++)
#pragma unroll
            for (int nf = 0; nf < 4; nf++) {
                const uint32_t* bh = &Bh[nf >> 1][(nf & 1) * 2];
                const uint32_t* bl = &Bl[nf >> 1][(nf & 1) * 2];
                hmma(acc[mf][nf], Ah[mf], bh);
                hmma(acc[mf][nf], Ah[mf], bl);
                hmma(acc[mf][nf], Al[mf], bh);
            }
    }
}

__device__ __forceinline__ void store_hilo2(__nv_bfloat16* oh, __nv_bfloat16* ol,
                                            size_t off, float c0, float c1) {
    __nv_bfloat162 h = __floats2bfloat162_rn(c0, c1);
    __nv_bfloat162 l = __floats2bfloat162_rn(c0 - __bfloat162float(h.x),
                                             c1 - __bfloat162float(h.y));
    *(__nv_bfloat162*)(oh + off) = h;
    *(__nv_bfloat162*)(ol + off) = l;
}
__device__ __forceinline__ void store_hilo1(__nv_bfloat16* oh, __nv_bfloat16* ol,
                                            size_t off, float c) {
    __nv_bfloat16 h = __float2bfloat16(c);
    oh[off] = h;
    ol[off] = __float2bfloat16(c - __bfloat162float(h));
}

// ---------------------------------------------------------------------------
// Kernel 0: W^T -> bf16 hi/lo planes
// ---------------------------------------------------------------------------
__global__ void prep_w(const float* __restrict__ Wq,
                       const float* __restrict__ Wk,
                       const float* __restrict__ Wv)
{
    const int z = blockIdx.y;
    const float* W = (z == 0) ? Wq : (z == 1) ? Wk : Wv;
    const int idx = blockIdx.x * 256 + threadIdx.x;
    const int n = idx >> 10, k = idx & 1023;
    float v = W[k * Hh + n];
    __nv_bfloat16 h = __float2bfloat16(v);
    g_Wt_hi[z * Hh * Ee + idx] = h;
    g_Wt_lo[z * Hh * Ee + idx] = __float2bfloat16(v - __bfloat162float(h));
}

// ---------------------------------------------------------------------------
// Kernel 1: QKV projection via HMMA (validated R5)
// ---------------------------------------------------------------------------
__global__ __launch_bounds__(256) void qkv_hmma(const float* __restrict__ x)
{
    extern __shared__ char smc[];
    const int z  = blockIdx.y;
    const int m0 = blockIdx.x * 128;
    const int tid = threadIdx.x, lane = tid & 31, wid = tid >> 5;
    const int wm = wid >> 2, wn = wid & 3;
    const uint32_t sA = smem_u32(smc);
    const uint32_t sB = sA + 2 * PLANE;

    const __nv_bfloat16* wh = g_Wt_hi + z * Hh * Ee;
    const __nv_bfloat16* wl = g_Wt_lo + z * Hh * Ee;

    float acc[4][4][4] = {};

    for (int k0 = 0; k0 < Ee; k0 += 64) {
#pragma unroll
        for (int i = 0; i < 8; i++) {
            int id = tid + i * 256;
            int r = id >> 4, ch = id & 15;
            float4 v = *(const float4*)(x + (size_t)(m0 + r) * Ee + k0 + ch * 4);
            __nv_bfloat162 h0 = __floats2bfloat162_rn(v.x, v.y);
            __nv_bfloat162 h1 = __floats2bfloat162_rn(v.z, v.w);
            __nv_bfloat162 l0 = __floats2bfloat162_rn(v.x - __bfloat162float(h0.x),
                                                      v.y - __bfloat162float(h0.y));
            __nv_bfloat162 l1 = __floats2bfloat162_rn(v.z - __bfloat162float(h1.x),
                                                      v.w - __bfloat162float(h1.y));
            char* p = smc + (r * STRIDE + ch * 4) * 2;
            *(uint2*)p = make_uint2(*(uint32_t*)&h0, *(uint32_t*)&h1);
            *(uint2*)(p + PLANE) = make_uint2(*(uint32_t*)&l0, *(uint32_t*)&l1);
        }
#pragma unroll
        for (int i = 0; i < 4; i++) {
            int id = tid + i * 256;
            int n = id >> 3, ch = id & 7;
            char* p = smc + 2 * PLANE + (n * STRIDE + ch * 8) * 2;
            *(float4*)p           = *(const float4*)(wh + (size_t)n * Ee + k0 + ch * 8);
            *(float4*)(p + PLANE) = *(const float4*)(wl + (size_t)n * Ee + k0 + ch * 8);
        }
        __syncthreads();
        mma_chunk(sA, sB, acc, wm, wn, lane);
        __syncthreads();
    }

    const int gid = lane >> 2, tig = lane & 3;
    if (z < 2) {
        __nv_bfloat16* oh = z ? g_Khi : g_Qhi;
        __nv_bfloat16* ol = z ? g_Klo : g_Qlo;
#pragma unroll
        for (int mf = 0; mf < 4; mf++)
#pragma unroll
            for (int nf = 0; nf < 4; nf++) {
                int col = wn * 32 + nf * 8 + tig * 2;
                int r0  = m0 + wm * 64 + mf * 16 + gid;
                store_hilo2(oh, ol, (size_t)r0 * Hh + col,
                            acc[mf][nf][0], acc[mf][nf][1]);
                store_hilo2(oh, ol, (size_t)(r0 + 8) * Hh + col,
                            acc[mf][nf][2], acc[mf][nf][3]);
            }
    } else {
#pragma unroll
        for (int mf = 0; mf < 4; mf++)
#pragma unroll
            for (int nf = 0; nf < 4; nf++) {
                int n  = wn * 32 + nf * 8 + tig * 2;
                int r0 = m0 + wm * 64 + mf * 16 + gid;
                store_hilo1(g_Vthi, g_Vtlo, (size_t)n * MTOT + r0,           acc[mf][nf][0]);
                store_hilo1(g_Vthi, g_Vtlo, (size_t)(n + 1) * MTOT + r0,     acc[mf][nf][1]);
                store_hilo1(g_Vthi, g_Vtlo, (size_t)n * MTOT + r0 + 8,       acc[mf][nf][2]);
                store_hilo1(g_Vthi, g_Vtlo, (size_t)(n + 1) * MTOT + r0 + 8, acc[mf][nf][3]);
            }
    }
}

// ---------------------------------------------------------------------------
// Kernel 2: split-K flash attention chunk.  blockIdx.x = item*8 + b.
// Runs <=4 k-tiles of (b, qt); writes unnormalized partial O', m, l.
// ---------------------------------------------------------------------------
__global__ __launch_bounds__(256) void attn_split(float* __restrict__ dummy)
{
    const int gi = blockIdx.x;
    const int it = gi >> 3;           // item within batch (0..39)
    const int b  = gi & 7;
    const int qt = WK_QT[it];
    const int c0 = WK_C0[it];
    const int nk = WK_NK[it];

    extern __shared__ char smc[];
    const int tid = threadIdx.x, lane = tid & 31, wid = tid >> 5;
    const int gid = lane >> 2, tig = lane & 3;

    const uint32_t sQ = smem_u32(smc);
    const uint32_t sK = sQ + 2 * FPL;
    const uint32_t sV = sQ + 4 * FPL;

    // Q tile resident (hi/lo)
    const int qb = b * Tt + qt * 128;
#pragma unroll
    for (int i = 0; i < 8; i++) {
        int id = tid + i * 256;
        int r = id >> 4, col = (id & 15) * 8;
        char* p = smc + (r * FSTR + col) * 2;
        *(float4*)p         = *(const float4*)(g_Qhi + (size_t)(qb + r) * Hh + col);
        *(float4*)(p + FPL) = *(const float4*)(g_Qlo + (size_t)(qb + r) * Hh + col);
    }

    float Oa[16][4] = {};
    float m0 = -INFINITY, m1 = -INFINITY, l0 = 0.f, l1 = 0.f;

    const int aRow = (lane & 7) + ((lane >> 3) & 1) * 8;
    const int aCol = ((lane >> 4) & 1) * 8;
    const int bRow = (lane & 7) + ((lane >> 4) & 1) * 8;
    const int bCol = ((lane >> 3) & 1) * 8;

    const int r0w = wid * 16 + gid;

    for (int kt = c0; kt < c0 + nk; kt++) {
        const int kb = b * Tt + kt * 128;
#pragma unroll
        for (int i = 0; i < 8; i++) {
            int id = tid + i * 256;
            int r = id >> 4, col = (id & 15) * 8;
            char* pk = smc + 2 * FPL + (r * FSTR + col) * 2;
            *(float4*)pk         = *(const float4*)(g_Khi + (size_t)(kb + r) * Hh + col);
            *(float4*)(pk + FPL) = *(const float4*)(g_Klo + (size_t)(kb + r) * Hh + col);
            char* pv = smc + 4 * FPL + (r * FSTR + col) * 2;
            *(float4*)pv         = *(const float4*)(g_Vthi + (size_t)r * MTOT + kb + col);
            *(float4*)(pv + FPL) = *(const float4*)(g_Vtlo + (size_t)r * MTOT + kb + col);
        }
        __syncthreads();

        // ---- S = Q K^T (3-term split) ----
        float Sa[16][4] = {};
#pragma unroll
        for (int kc = 0; kc < 8; kc++) {
            uint32_t Ah[4], Al[4];
            uint32_t ad = sQ + (uint32_t)((wid * 16 + aRow) * FSTR + kc * 16 + aCol) * 2;
            ldsm4(Ah[0], Ah[1], Ah[2], Ah[3], ad);
            ldsm4(Al[0], Al[1], Al[2], Al[3], ad + FPL);
#pragma unroll
            for (int ng = 0; ng < 8; ng++) {
                uint32_t Bh[4], Bl[4];
                uint32_t bd = sK + (uint32_t)((ng * 16 + bRow) * FSTR + kc * 16 + bCol) * 2;
                ldsm4(Bh[0], Bh[1], Bh[2], Bh[3], bd);
                ldsm4(Bl[0], Bl[1], Bl[2], Bl[3], bd + FPL);
#pragma unroll
                for (int j = 0; j < 2; j++) {
                    hmma(Sa[ng * 2 + j], Ah, &Bh[2 * j]);
                    hmma(Sa[ng * 2 + j], Ah, &Bl[2 * j]);
                    hmma(Sa[ng * 2 + j], Al, &Bh[2 * j]);
                }
            }
        }

        // ---- scale + causal mask + online softmax ----
        const bool diag = (kt == qt);
        float bm0 = -INFINITY, bm1 = -INFINITY;
#pragma unroll
        for (int nf = 0; nf < 16; nf++) {
            int c = nf * 8 + tig * 2;
            float v0 = Sa[nf][0] * SC2, v1 = Sa[nf][1] * SC2;
            float v2 = Sa[nf][2] * SC2, v3 = Sa[nf][3] * SC2;
            if (diag) {
                if (c     > r0w)     v0 = -INFINITY;
                if (c + 1 > r0w)     v1 = -INFINITY;
                if (c     > r0w + 8) v2 = -INFINITY;
                if (c + 1 > r0w + 8) v3 = -INFINITY;
            }
            Sa[nf][0] = v0; Sa[nf][1] = v1; Sa[nf][2] = v2; Sa[nf][3] = v3;
            bm0 = fmaxf(bm0, fmaxf(v0, v1));
            bm1 = fmaxf(bm1, fmaxf(v2, v3));
        }
        bm0 = fmaxf(bm0, __shfl_xor_sync(0xFFFFFFFFu, bm0, 1));
        bm0 = fmaxf(bm0, __shfl_xor_sync(0xFFFFFFFFu, bm0, 2));
        bm1 = fmaxf(bm1, __shfl_xor_sync(0xFFFFFFFFu, bm1, 1));
        bm1 = fmaxf(bm1, __shfl_xor_sync(0xFFFFFFFFu, bm1, 2));

        float nm0 = fmaxf(m0, bm0), nm1 = fmaxf(m1, bm1);
        float a0 = exp2f(m0 - nm0), a1 = exp2f(m1 - nm1);
        m0 = nm0; m1 = nm1;

        float s0 = 0.f, s1 = 0.f;
#pragma unroll
        for (int nf = 0; nf < 16; nf++) {
            Sa[nf][0] = exp2f(Sa[nf][0] - nm0);
            Sa[nf][1] = exp2f(Sa[nf][1] - nm0);
            Sa[nf][2] = exp2f(Sa[nf][2] - nm1);
            Sa[nf][3] = exp2f(Sa[nf][3] - nm1);
            s0 += Sa[nf][0] + Sa[nf][1];
            s1 += Sa[nf][2] + Sa[nf][3];
        }
        s0 += __shfl_xor_sync(0xFFFFFFFFu, s0, 1);
        s0 += __shfl_xor_sync(0xFFFFFFFFu, s0, 2);
        s1 += __shfl_xor_sync(0xFFFFFFFFu, s1, 1);
        s1 += __shfl_xor_sync(0xFFFFFFFFu, s1, 2);
        l0 = l0 * a0 + s0;
        l1 = l1 * a1 + s1;

#pragma unroll
        for (int nf = 0; nf < 16; nf++) {
            Oa[nf][0] *= a0; Oa[nf][1] *= a0;
            Oa[nf][2] *= a1; Oa[nf][3] *= a1;
        }

        // ---- O += P V (3-term) ----
#pragma unroll
        for (int kc = 0; kc < 8; kc++) {
            uint32_t Ph[4], Pl[4];
            pack_hilo(Ph[0], Pl[0], Sa[2 * kc][0],     Sa[2 * kc][1]);
            pack_hilo(Ph[1], Pl[1], Sa[2 * kc][2],     Sa[2 * kc][3]);
            pack_hilo(Ph[2], Pl[2], Sa[2 * kc + 1][0], Sa[2 * kc + 1][1]);
            pack_hilo(Ph[3], Pl[3], Sa[2 * kc + 1][2], Sa[2 * kc + 1][3]);
#pragma unroll
            for (int ng = 0; ng < 8; ng++) {
                uint32_t Vh[4], Vl[4];
                uint32_t bd = sV + (uint32_t)((ng * 16 + bRow) * FSTR + kc * 16 + bCol) * 2;
                ldsm4(Vh[0], Vh[1], Vh[2], Vh[3], bd);
                ldsm4(Vl[0], Vl[1], Vl[2], Vl[3], bd + FPL);
#pragma unroll
                for (int j = 0; j < 2; j++) {
                    hmma(Oa[ng * 2 + j], Ph, &Vh[2 * j]);
                    hmma(Oa[ng * 2 + j], Ph, &Vl[2 * j]);
                    hmma(Oa[ng * 2 + j], Pl, &Vh[2 * j]);
                }
            }
        }
        __syncthreads();
    }

    // ---- epilogue: write unnormalized partial + per-row m, l ----
    float* Op = g_Opart[gi];
#pragma unroll
    for (int nf = 0; nf < 16; nf++) {
        int col = nf * 8 + tig * 2;
        *(float2*)&Op[r0w * 128 + col]       = make_float2(Oa[nf][0], Oa[nf][1]);
        *(float2*)&Op[(r0w + 8) * 128 + col] = make_float2(Oa[nf][2], Oa[nf][3]);
    }
    if (tig == 0) {
        g_mpart[gi][r0w]     = m0;
        g_lpart[gi][r0w]     = l0;
        g_mpart[gi][r0w + 8] = m1;
        g_lpart[gi][r0w + 8] = l1;
    }
}

// ---------------------------------------------------------------------------
// Kernel 3: merge partials.  grid (16 qt, 8 b), 256 threads.
// Thread = (row, half): combines <=4 chunks for its 64 columns.
// ---------------------------------------------------------------------------
__global__ __launch_bounds__(256) void attn_merge(float* __restrict__ out)
{
    const int qt = blockIdx.x, b = blockIdx.y;
    const int nch = QT_NCH[qt];

    const int tid = threadIdx.x;
    const int r   = tid >> 1;
    const int co  = (tid & 1) * 64;

    int gi[4];
    float mv[4];
    float mmax = -INFINITY;
#pragma unroll
    for (int j = 0; j < 4; j++) {
        if (j < nch) {
            gi[j] = QT_ITEMS[qt][j] * 8 + b;
            mv[j] = g_mpart[gi[j]][r];
            mmax  = fmaxf(mmax, mv[j]);
        }
    }
    float a[4];
    float lsum = 0.f;
#pragma unroll
    for (int j = 0; j < 4; j++) {
        if (j < nch) {
            a[j] = exp2f(mv[j] - mmax);
            lsum += a[j] * g_lpart[gi[j]][r];
        }
    }
    const float inv = 1.f / lsum;

    float* orow = out + ((size_t)(b * Tt + qt * 128 + r)) * Hh + co;
#pragma unroll
    for (int c = 0; c < 16; c++) {
        float4 acc = make_float4(0.f, 0.f, 0.f, 0.f);
#pragma unroll
        for (int j = 0; j < 4; j++) {
            if (j < nch) {
                float4 v = *(const float4*)&g_Opart[gi[j]][r * 128 + co + c * 4];
                acc.x += a[j] * v.x;
                acc.y += a[j] * v.y;
                acc.z += a[j] * v.z;
                acc.w += a[j] * v.w;
            }
        }
        acc.x *= inv; acc.y *= inv; acc.z *= inv; acc.w *= inv;
        *(float4*)&orow[c * 4] = acc;
    }
}

// ---------------------------------------------------------------------------
extern "C" void kernel_launch(void* const* d_in, const int* in_sizes, int n_in,
                              void* d_out, int out_size)
{
    const float* x  = (const float*)d_in[0];
    const float* Wq = (const float*)d_in[1];
    const float* Wk = (const float*)d_in[2];
    const float* Wv = (const float*)d_in[3];
    float* out = (float*)d_out;

    const int SMEM_QKV  = 4 * PLANE;   // 73728
    const int SMEM_ATTN = 6 * FPL;     // 208896
    cudaFuncSetAttribute(qkv_hmma,   cudaFuncAttributeMaxDynamicSharedMemorySize, SMEM_QKV);
    cudaFuncSetAttribute(attn_split, cudaFuncAttributeMaxDynamicSharedMemorySize, SMEM_ATTN);

    prep_w<<<dim3(512, 3), 256>>>(Wq, Wk, Wv);
    qkv_hmma<<<dim3(128, 3), 256, SMEM_QKV>>>(x);
    attn_split<<<NCTA, 256, SMEM_ATTN>>>(out);
    attn_merge<<<dim3(16, 8), 256>>>(out);
}

// round 8
// speedup vs baseline: 5.2240x; 1.3117x over previous
#include <cuda_runtime.h>
#include <cuda_fp16.h>
#include <math.h>
#include <cstdint>

#define Bb 8
#define Tt 2048
#define Ee 1024
#define Hh 128
#define MTOT (Bb * Tt)               // 16384
// scale * log2(e): softmax computed in exp2 domain
#define SC2 0.1275174306f

#define STRIDE 72                    // qkv kernel SMEM row stride (64 data + 8 pad)
#define PLANE  (128 * STRIDE * 2)    // 18432 B

#define FSTR 136                     // attn kernel row stride (128 data + 8 pad)
#define FPL  (128 * FSTR * 2)        // 34816 B per [128 x 128] fp16 plane

#define NITEMS 40
#define NCTA   (NITEMS * Bb)         // 320

// ---------------------------------------------------------------------------
// Device scratch
// ---------------------------------------------------------------------------
__device__ __half g_Wt[3 * Hh * Ee];                  // W^T hi only
__device__ __half g_Qhi[MTOT * Hh], g_Qlo[MTOT * Hh]; // Q: A operand, 2-plane
__device__ __half g_K[MTOT * Hh];                     // K: B operand, hi only
__device__ __half g_Vt[Hh * MTOT];                    // V^T: B operand, hi only

__device__ float g_Opart[NCTA][128 * 128];
__device__ float g_mpart[NCTA][128];
__device__ float g_lpart[NCTA][128];

// Work tables (validated R7)
__device__ const int WK_QT[NITEMS] = {
    3,4,5,6,7,7,8,8,9,9,10,10,11,11,11,12,12,12,13,13,13,14,14,14,15,15,15,15,
    2,6,10,14,  1,5,9,13,  0,4,8,12};
__device__ const int WK_C0[NITEMS] = {
    0,0,0,0,0,4,0,4,0,4,0,4,0,4,8,0,4,8,0,4,8,0,4,8,0,4,8,12,
    0,4,8,12,  0,4,8,12,  0,4,8,12};
__device__ const int WK_NK[NITEMS] = {
    4,4,4,4,4,4,4,4,4,4,4,4,4,4,4,4,4,4,4,4,4,4,4,4,4,4,4,4,
    3,3,3,3,  2,2,2,2,  1,1,1,1};
__device__ const int QT_NCH[16] = {1,1,1,1,2,2,2,2,3,3,3,3,4,4,4,4};
__device__ const int QT_ITEMS[16][4] = {
    {36,0,0,0},{32,0,0,0},{28,0,0,0},{0,0,0,0},
    {1,37,0,0},{2,33,0,0},{3,29,0,0},{4,5,0,0},
    {6,7,38,0},{8,9,34,0},{10,11,30,0},{12,13,14,0},
    {15,16,17,39},{18,19,20,35},{21,22,23,31},{24,25,26,27}};

// ---------------------------------------------------------------------------
// PTX helpers
// ---------------------------------------------------------------------------
__device__ __forceinline__ uint32_t smem_u32(const void* p) {
    uint32_t a;
    asm("{ .reg .u64 t; cvta.to.shared.u64 t, %1; cvt.u32.u64 %0, t; }"
        : "=r"(a) : "l"(p));
    return a;
}
__device__ __forceinline__ void ldsm4(uint32_t& r0, uint32_t& r1,
                                      uint32_t& r2, uint32_t& r3, uint32_t addr) {
    asm volatile("ldmatrix.sync.aligned.m8n8.x4.shared.b16 {%0,%1,%2,%3}, [%4];"
                 : "=r"(r0), "=r"(r1), "=r"(r2), "=r"(r3) : "r"(addr));
}
__device__ __forceinline__ void hmma(float* c, const uint32_t* a, const uint32_t* b) {
    asm volatile(
        "mma.sync.aligned.m16n8k16.row.col.f32.f16.f16.f32 "
        "{%0,%1,%2,%3}, {%4,%5,%6,%7}, {%8,%9}, {%0,%1,%2,%3};"
        : "+f"(c[0]), "+f"(c[1]), "+f"(c[2]), "+f"(c[3])
        : "r"(a[0]), "r"(a[1]), "r"(a[2]), "r"(a[3]), "r"(b[0]), "r"(b[1]));
}
__device__ __forceinline__ void pack_hilo(uint32_t& h, uint32_t& l, float x, float y) {
    __half2 hh = __floats2half2_rn(x, y);
    __half2 ll = __floats2half2_rn(x - __low2float(hh), y - __high2float(hh));
    h = *(uint32_t*)&hh;
    l = *(uint32_t*)&ll;
}

// ---------------------------------------------------------------------------
// qkv mainloop chunk: 2-term fp16 (Ah+Al)*Bh, single B plane
// ---------------------------------------------------------------------------
__device__ __forceinline__ void mma_chunk(uint32_t sA, uint32_t sB,
                                          float acc[4][4][4],
                                          int wm, int wn, int lane)
{
    const int aRow = (lane & 7) + ((lane >> 3) & 1) * 8;
    const int aCol = ((lane >> 4) & 1) * 8;
    const int bRow = (lane & 7) + ((lane >> 4) & 1) * 8;
    const int bCol = ((lane >> 3) & 1) * 8;

#pragma unroll
    for (int ks = 0; ks < 4; ks++) {
        uint32_t Ah[4][4], Al[4][4], Bh[2][4];
#pragma unroll
        for (int mf = 0; mf < 4; mf++) {
            uint32_t ad = sA + (uint32_t)((wm * 64 + mf * 16 + aRow) * STRIDE
                                          + ks * 16 + aCol) * 2;
            ldsm4(Ah[mf][0], Ah[mf][1], Ah[mf][2], Ah[mf][3], ad);
            ldsm4(Al[mf][0], Al[mf][1], Al[mf][2], Al[mf][3], ad + PLANE);
        }
#pragma unroll
        for (int np = 0; np < 2; np++) {
            uint32_t bd = sB + (uint32_t)((wn * 32 + np * 16 + bRow) * STRIDE
                                          + ks * 16 + bCol) * 2;
            ldsm4(Bh[np][0], Bh[np][1], Bh[np][2], Bh[np][3], bd);
        }
#pragma unroll
        for (int mf = 0; mf < 4; mf++)
#pragma unroll
            for (int nf = 0; nf < 4; nf++) {
                const uint32_t* bh = &Bh[nf >> 1][(nf & 1) * 2];
                hmma(acc[mf][nf], Ah[mf], bh);
                hmma(acc[mf][nf], Al[mf], bh);
            }
    }
}

// ---------------------------------------------------------------------------
// Kernel 0: W^T -> fp16 (hi only)
// ---------------------------------------------------------------------------
__global__ void prep_w(const float* __restrict__ Wq,
                       const float* __restrict__ Wk,
                       const float* __restrict__ Wv)
{
    const int z = blockIdx.y;
    const float* W = (z == 0) ? Wq : (z == 1) ? Wk : Wv;
    const int idx = blockIdx.x * 256 + threadIdx.x;
    const int n = idx >> 10, k = idx & 1023;
    g_Wt[z * Hh * Ee + idx] = __float2half(W[k * Hh + n]);
}

// ---------------------------------------------------------------------------
// Kernel 1: QKV projection.  grid (3 z, 128 m) — z fastest for x L2 reuse.
// ---------------------------------------------------------------------------
__global__ __launch_bounds__(256) void qkv_hmma(const float* __restrict__ x)
{
    extern __shared__ char smc[];
    const int z  = blockIdx.x;
    const int m0 = blockIdx.y * 128;
    const int tid = threadIdx.x, lane = tid & 31, wid = tid >> 5;
    const int wm = wid >> 2, wn = wid & 3;
    const uint32_t sA = smem_u32(smc);
    const uint32_t sB = sA + 2 * PLANE;

    const __half* wh = g_Wt + z * Hh * Ee;

    float acc[4][4][4] = {};

    for (int k0 = 0; k0 < Ee; k0 += 64) {
        // A: x fp32 [128 x 64] -> fp16 hi/lo
#pragma unroll
        for (int i = 0; i < 8; i++) {
            int id = tid + i * 256;
            int r = id >> 4, ch = id & 15;
            float4 v = *(const float4*)(x + (size_t)(m0 + r) * Ee + k0 + ch * 4);
            __half2 h0 = __floats2half2_rn(v.x, v.y);
            __half2 h1 = __floats2half2_rn(v.z, v.w);
            __half2 l0 = __floats2half2_rn(v.x - __low2float(h0), v.y - __high2float(h0));
            __half2 l1 = __floats2half2_rn(v.z - __low2float(h1), v.w - __high2float(h1));
            char* p = smc + (r * STRIDE + ch * 4) * 2;
            *(uint2*)p           = make_uint2(*(uint32_t*)&h0, *(uint32_t*)&h1);
            *(uint2*)(p + PLANE) = make_uint2(*(uint32_t*)&l0, *(uint32_t*)&l1);
        }
        // B: W^T fp16 single plane
#pragma unroll
        for (int i = 0; i < 4; i++) {
            int id = tid + i * 256;
            int n = id >> 3, ch = id & 7;
            char* p = smc + 2 * PLANE + (n * STRIDE + ch * 8) * 2;
            *(float4*)p = *(const float4*)(wh + (size_t)n * Ee + k0 + ch * 8);
        }
        __syncthreads();
        mma_chunk(sA, sB, acc, wm, wn, lane);
        __syncthreads();
    }

    const int gid = lane >> 2, tig = lane & 3;
    if (z == 0) {
        // Q: hi/lo fp16 planes
#pragma unroll
        for (int mf = 0; mf < 4; mf++)
#pragma unroll
            for (int nf = 0; nf < 4; nf++) {
                int col = wn * 32 + nf * 8 + tig * 2;
                int r0  = m0 + wm * 64 + mf * 16 + gid;
                uint32_t h, l;
                pack_hilo(h, l, acc[mf][nf][0], acc[mf][nf][1]);
                *(uint32_t*)&g_Qhi[(size_t)r0 * Hh + col] = h;
                *(uint32_t*)&g_Qlo[(size_t)r0 * Hh + col] = l;
                pack_hilo(h, l, acc[mf][nf][2], acc[mf][nf][3]);
                *(uint32_t*)&g_Qhi[(size_t)(r0 + 8) * Hh + col] = h;
                *(uint32_t*)&g_Qlo[(size_t)(r0 + 8) * Hh + col] = l;
            }
    } else if (z == 1) {
        // K: hi only
#pragma unroll
        for (int mf = 0; mf < 4; mf++)
#pragma unroll
            for (int nf = 0; nf < 4; nf++) {
                int col = wn * 32 + nf * 8 + tig * 2;
                int r0  = m0 + wm * 64 + mf * 16 + gid;
                *(__half2*)&g_K[(size_t)r0 * Hh + col] =
                    __floats2half2_rn(acc[mf][nf][0], acc[mf][nf][1]);
                *(__half2*)&g_K[(size_t)(r0 + 8) * Hh + col] =
                    __floats2half2_rn(acc[mf][nf][2], acc[mf][nf][3]);
            }
    } else {
        // V transposed, hi only: g_Vt[h][token]
#pragma unroll
        for (int mf = 0; mf < 4; mf++)
#pragma unroll
            for (int nf = 0; nf < 4; nf++) {
                int n  = wn * 32 + nf * 8 + tig * 2;
                int r0 = m0 + wm * 64 + mf * 16 + gid;
                g_Vt[(size_t)n * MTOT + r0]           = __float2half(acc[mf][nf][0]);
                g_Vt[(size_t)(n + 1) * MTOT + r0]     = __float2half(acc[mf][nf][1]);
                g_Vt[(size_t)n * MTOT + r0 + 8]       = __float2half(acc[mf][nf][2]);
                g_Vt[(size_t)(n + 1) * MTOT + r0 + 8] = __float2half(acc[mf][nf][3]);
            }
    }
}

// ---------------------------------------------------------------------------
// Kernel 2: split-K flash attention chunk.  SMEM: Q hi/lo, K hi, V^T hi.
// ---------------------------------------------------------------------------
__global__ __launch_bounds__(256) void attn_split()
{
    const int gi = blockIdx.x;
    const int it = gi >> 3;
    const int b  = gi & 7;
    const int qt = WK_QT[it];
    const int c0 = WK_C0[it];
    const int nk = WK_NK[it];

    extern __shared__ char smc[];
    const int tid = threadIdx.x, lane = tid & 31, wid = tid >> 5;
    const int gid = lane >> 2, tig = lane & 3;

    const uint32_t sQ = smem_u32(smc);
    const uint32_t sK = sQ + 2 * FPL;
    const uint32_t sV = sQ + 3 * FPL;

    // Q tile resident (hi/lo)
    const int qb = b * Tt + qt * 128;
#pragma unroll
    for (int i = 0; i < 8; i++) {
        int id = tid + i * 256;
        int r = id >> 4, col = (id & 15) * 8;
        char* p = smc + (r * FSTR + col) * 2;
        *(float4*)p         = *(const float4*)(g_Qhi + (size_t)(qb + r) * Hh + col);
        *(float4*)(p + FPL) = *(const float4*)(g_Qlo + (size_t)(qb + r) * Hh + col);
    }

    float Oa[16][4] = {};
    float m0 = -INFINITY, m1 = -INFINITY, l0 = 0.f, l1 = 0.f;

    const int aRow = (lane & 7) + ((lane >> 3) & 1) * 8;
    const int aCol = ((lane >> 4) & 1) * 8;
    const int bRow = (lane & 7) + ((lane >> 4) & 1) * 8;
    const int bCol = ((lane >> 3) & 1) * 8;

    const int r0w = wid * 16 + gid;

    for (int kt = c0; kt < c0 + nk; kt++) {
        const int kb = b * Tt + kt * 128;
#pragma unroll
        for (int i = 0; i < 8; i++) {
            int id = tid + i * 256;
            int r = id >> 4, col = (id & 15) * 8;
            *(float4*)(smc + 2 * FPL + (r * FSTR + col) * 2) =
                *(const float4*)(g_K + (size_t)(kb + r) * Hh + col);
            *(float4*)(smc + 3 * FPL + (r * FSTR + col) * 2) =
                *(const float4*)(g_Vt + (size_t)r * MTOT + kb + col);
        }
        __syncthreads();

        // ---- S = Q K^T (2-term fp16) ----
        float Sa[16][4] = {};
#pragma unroll
        for (int kc = 0; kc < 8; kc++) {
            uint32_t Ah[4], Al[4];
            uint32_t ad = sQ + (uint32_t)((wid * 16 + aRow) * FSTR + kc * 16 + aCol) * 2;
            ldsm4(Ah[0], Ah[1], Ah[2], Ah[3], ad);
            ldsm4(Al[0], Al[1], Al[2], Al[3], ad + FPL);
#pragma unroll
            for (int ng = 0; ng < 8; ng++) {
                uint32_t Bh[4];
                uint32_t bd = sK + (uint32_t)((ng * 16 + bRow) * FSTR + kc * 16 + bCol) * 2;
                ldsm4(Bh[0], Bh[1], Bh[2], Bh[3], bd);
#pragma unroll
                for (int j = 0; j < 2; j++) {
                    hmma(Sa[ng * 2 + j], Ah, &Bh[2 * j]);
                    hmma(Sa[ng * 2 + j], Al, &Bh[2 * j]);
                }
            }
        }

        // ---- scale + causal mask + online softmax ----
        const bool diag = (kt == qt);
        float bm0 = -INFINITY, bm1 = -INFINITY;
#pragma unroll
        for (int nf = 0; nf < 16; nf++) {
            int c = nf * 8 + tig * 2;
            float v0 = Sa[nf][0] * SC2, v1 = Sa[nf][1] * SC2;
            float v2 = Sa[nf][2] * SC2, v3 = Sa[nf][3] * SC2;
            if (diag) {
                if (c     > r0w)     v0 = -INFINITY;
                if (c + 1 > r0w)     v1 = -INFINITY;
                if (c     > r0w + 8) v2 = -INFINITY;
                if (c + 1 > r0w + 8) v3 = -INFINITY;
            }
            Sa[nf][0] = v0; Sa[nf][1] = v1; Sa[nf][2] = v2; Sa[nf][3] = v3;
            bm0 = fmaxf(bm0, fmaxf(v0, v1));
            bm1 = fmaxf(bm1, fmaxf(v2, v3));
        }
        bm0 = fmaxf(bm0, __shfl_xor_sync(0xFFFFFFFFu, bm0, 1));
        bm0 = fmaxf(bm0, __shfl_xor_sync(0xFFFFFFFFu, bm0, 2));
        bm1 = fmaxf(bm1, __shfl_xor_sync(0xFFFFFFFFu, bm1, 1));
        bm1 = fmaxf(bm1, __shfl_xor_sync(0xFFFFFFFFu, bm1, 2));

        float nm0 = fmaxf(m0, bm0), nm1 = fmaxf(m1, bm1);
        float a0 = exp2f(m0 - nm0), a1 = exp2f(m1 - nm1);
        m0 = nm0; m1 = nm1;

        float s0 = 0.f, s1 = 0.f;
#pragma unroll
        for (int nf = 0; nf < 16; nf++) {
            Sa[nf][0] = exp2f(Sa[nf][0] - nm0);
            Sa[nf][1] = exp2f(Sa[nf][1] - nm0);
            Sa[nf][2] = exp2f(Sa[nf][2] - nm1);
            Sa[nf][3] = exp2f(Sa[nf][3] - nm1);
            s0 += Sa[nf][0] + Sa[nf][1];
            s1 += Sa[nf][2] + Sa[nf][3];
        }
        s0 += __shfl_xor_sync(0xFFFFFFFFu, s0, 1);
        s0 += __shfl_xor_sync(0xFFFFFFFFu, s0, 2);
        s1 += __shfl_xor_sync(0xFFFFFFFFu, s1, 1);
        s1 += __shfl_xor_sync(0xFFFFFFFFu, s1, 2);
        l0 = l0 * a0 + s0;
        l1 = l1 * a1 + s1;

#pragma unroll
        for (int nf = 0; nf < 16; nf++) {
            Oa[nf][0] *= a0; Oa[nf][1] *= a0;
            Oa[nf][2] *= a1; Oa[nf][3] *= a1;
        }

        // ---- O += P V (2-term fp16: (Ph+Pl)*Vh) ----
#pragma unroll
        for (int kc = 0; kc < 8; kc++) {
            uint32_t Ph[4], Pl[4];
            pack_hilo(Ph[0], Pl[0], Sa[2 * kc][0],     Sa[2 * kc][1]);
            pack_hilo(Ph[1], Pl[1], Sa[2 * kc][2],     Sa[2 * kc][3]);
            pack_hilo(Ph[2], Pl[2], Sa[2 * kc + 1][0], Sa[2 * kc + 1][1]);
            pack_hilo(Ph[3], Pl[3], Sa[2 * kc + 1][2], Sa[2 * kc + 1][3]);
#pragma unroll
            for (int ng = 0; ng < 8; ng++) {
                uint32_t Vh[4];
                uint32_t bd = sV + (uint32_t)((ng * 16 + bRow) * FSTR + kc * 16 + bCol) * 2;
                ldsm4(Vh[0], Vh[1], Vh[2], Vh[3], bd);
#pragma unroll
                for (int j = 0; j < 2; j++) {
                    hmma(Oa[ng * 2 + j], Ph, &Vh[2 * j]);
                    hmma(Oa[ng * 2 + j], Pl, &Vh[2 * j]);
                }
            }
        }
        __syncthreads();
    }

    // ---- epilogue: write unnormalized partial + per-row m, l ----
    float* Op = g_Opart[gi];
#pragma unroll
    for (int nf = 0; nf < 16; nf++) {
        int col = nf * 8 + tig * 2;
        *(float2*)&Op[r0w * 128 + col]       = make_float2(Oa[nf][0], Oa[nf][1]);
        *(float2*)&Op[(r0w + 8) * 128 + col] = make_float2(Oa[nf][2], Oa[nf][3]);
    }
    if (tig == 0) {
        g_mpart[gi][r0w]     = m0;
        g_lpart[gi][r0w]     = l0;
        g_mpart[gi][r0w + 8] = m1;
        g_lpart[gi][r0w + 8] = l1;
    }
}

// ---------------------------------------------------------------------------
// Kernel 3: merge partials.  grid (16 qt, 8 b, 4 row-groups), 256 threads.
// Thread = (row within group, col-chunk of 16).
// ---------------------------------------------------------------------------
__global__ __launch_bounds__(256) void attn_merge(float* __restrict__ out)
{
    const int qt = blockIdx.x, b = blockIdx.y, rg = blockIdx.z;
    const int nch = QT_NCH[qt];

    const int tid = threadIdx.x;
    const int r   = rg * 32 + (tid >> 3);
    const int co  = (tid & 7) * 16;

    int gi[4];
    float mv[4];
    float mmax = -INFINITY;
#pragma unroll
    for (int j = 0; j < 4; j++) {
        if (j < nch) {
            gi[j] = QT_ITEMS[qt][j] * 8 + b;
            mv[j] = g_mpart[gi[j]][r];
            mmax  = fmaxf(mmax, mv[j]);
        }
    }
    float a[4];
    float lsum = 0.f;
#pragma unroll
    for (int j = 0; j < 4; j++) {
        if (j < nch) {
            a[j] = exp2f(mv[j] - mmax);
            lsum += a[j] * g_lpart[gi[j]][r];
        }
    }
    const float inv = 1.f / lsum;

    float* orow = out + ((size_t)(b * Tt + qt * 128 + r)) * Hh + co;
#pragma unroll
    for (int c = 0; c < 4; c++) {
        float4 acc = make_float4(0.f, 0.f, 0.f, 0.f);
#pragma unroll
        for (int j = 0; j < 4; j++) {
            if (j < nch) {
                float4 v = *(const float4*)&g_Opart[gi[j]][r * 128 + co + c * 4];
                acc.x += a[j] * v.x;
                acc.y += a[j] * v.y;
                acc.z += a[j] * v.z;
                acc.w += a[j] * v.w;
            }
        }
        acc.x *= inv; acc.y *= inv; acc.z *= inv; acc.w *= inv;
        *(float4*)&orow[c * 4] = acc;
    }
}

// ---------------------------------------------------------------------------
extern "C" void kernel_launch(void* const* d_in, const int* in_sizes, int n_in,
                              void* d_out, int out_size)
{
    const float* x  = (const float*)d_in[0];
    const float* Wq = (const float*)d_in[1];
    const float* Wk = (const float*)d_in[2];
    const float* Wv = (const float*)d_in[3];
    float* out = (float*)d_out;

    const int SMEM_QKV  = 3 * PLANE;   // 55296
    const int SMEM_ATTN = 4 * FPL;     // 139264
    cudaFuncSetAttribute(qkv_hmma,   cudaFuncAttributeMaxDynamicSharedMemorySize, SMEM_QKV);
    cudaFuncSetAttribute(attn_split, cudaFuncAttributeMaxDynamicSharedMemorySize, SMEM_ATTN);

    prep_w<<<dim3(512, 3), 256>>>(Wq, Wk, Wv);
    qkv_hmma<<<dim3(3, 128), 256, SMEM_QKV>>>(x);
    attn_split<<<NCTA, 256, SMEM_ATTN>>>();
    attn_merge<<<dim3(16, 8, 4), 256>>>(out);
}

// round 9
// speedup vs baseline: 5.8831x; 1.1262x over previous
#include <cuda_runtime.h>
#include <cuda_fp16.h>
#include <math.h>
#include <cstdint>

#define Bb 8
#define Tt 2048
#define Ee 1024
#define Hh 128
#define MTOT (Bb * Tt)               // 16384
#define SC2 0.1275174306f            // scale * log2(e)

#define STRIDE 72                    // qkv SMEM row stride (halves)
#define PLANE  (128 * STRIDE * 2)    // 18432 B

#define FSTR 136                     // attn SMEM row stride (halves)
#define FPL  (128 * FSTR * 2)        // 34816 B per [128 x 128] fp16 plane

#define NITEMS 40
#define NCTA   (NITEMS * Bb)         // 320

// ---------------------------------------------------------------------------
// Device scratch
// ---------------------------------------------------------------------------
__device__ __half g_Wt[3 * Hh * Ee];                  // W^T hi only
__device__ __half g_Qhi[MTOT * Hh], g_Qlo[MTOT * Hh];
__device__ __half g_K[MTOT * Hh];
__device__ __half g_Vt[Hh * MTOT];                    // [128 h][16384 tok]

__device__ float g_Opart[NCTA][128 * 128];
__device__ float g_mpart[NCTA][128];
__device__ float g_lpart[NCTA][128];

// Work tables (validated R7/R8)
__device__ const int WK_QT[NITEMS] = {
    3,4,5,6,7,7,8,8,9,9,10,10,11,11,11,12,12,12,13,13,13,14,14,14,15,15,15,15,
    2,6,10,14,  1,5,9,13,  0,4,8,12};
__device__ const int WK_C0[NITEMS] = {
    0,0,0,0,0,4,0,4,0,4,0,4,0,4,8,0,4,8,0,4,8,0,4,8,0,4,8,12,
    0,4,8,12,  0,4,8,12,  0,4,8,12};
__device__ const int WK_NK[NITEMS] = {
    4,4,4,4,4,4,4,4,4,4,4,4,4,4,4,4,4,4,4,4,4,4,4,4,4,4,4,4,
    3,3,3,3,  2,2,2,2,  1,1,1,1};
__device__ const int QT_NCH[16] = {1,1,1,1,2,2,2,2,3,3,3,3,4,4,4,4};
__device__ const int QT_ITEMS[16][4] = {
    {36,0,0,0},{32,0,0,0},{28,0,0,0},{0,0,0,0},
    {1,37,0,0},{2,33,0,0},{3,29,0,0},{4,5,0,0},
    {6,7,38,0},{8,9,34,0},{10,11,30,0},{12,13,14,0},
    {15,16,17,39},{18,19,20,35},{21,22,23,31},{24,25,26,27}};

// ---------------------------------------------------------------------------
// PTX helpers
// ---------------------------------------------------------------------------
__device__ __forceinline__ uint32_t smem_u32(const void* p) {
    uint32_t a;
    asm("{ .reg .u64 t; cvta.to.shared.u64 t, %1; cvt.u32.u64 %0, t; }"
        : "=r"(a) : "l"(p));
    return a;
}
__device__ __forceinline__ void ldsm4(uint32_t& r0, uint32_t& r1,
                                      uint32_t& r2, uint32_t& r3, uint32_t addr) {
    asm volatile("ldmatrix.sync.aligned.m8n8.x4.shared.b16 {%0,%1,%2,%3}, [%4];"
                 : "=r"(r0), "=r"(r1), "=r"(r2), "=r"(r3) : "r"(addr));
}
__device__ __forceinline__ void hmma(float* c, const uint32_t* a, const uint32_t* b) {
    asm volatile(
        "mma.sync.aligned.m16n8k16.row.col.f32.f16.f16.f32 "
        "{%0,%1,%2,%3}, {%4,%5,%6,%7}, {%8,%9}, {%0,%1,%2,%3};"
        : "+f"(c[0]), "+f"(c[1]), "+f"(c[2]), "+f"(c[3])
        : "r"(a[0]), "r"(a[1]), "r"(a[2]), "r"(a[3]), "r"(b[0]), "r"(b[1]));
}
__device__ __forceinline__ void pack_hilo(uint32_t& h, uint32_t& l, float x, float y) {
    __half2 hh = __floats2half2_rn(x, y);
    __half2 ll = __floats2half2_rn(x - __low2float(hh), y - __high2float(hh));
    h = *(uint32_t*)&hh;
    l = *(uint32_t*)&ll;
}
__device__ __forceinline__ void cpa16(uint32_t d, const void* s) {
    asm volatile("cp.async.cg.shared.global [%0], [%1], 16;" :: "r"(d), "l"(s));
}
#define CPA_COMMIT() asm volatile("cp.async.commit_group;" ::: "memory")
#define CPA_WAIT0()  asm volatile("cp.async.wait_group 0;" ::: "memory")
#define CPA_WAIT1()  asm volatile("cp.async.wait_group 1;" ::: "memory")

// ---------------------------------------------------------------------------
// qkv mainloop chunk: 2-term fp16 (Ah+Al)*Bh.  A hi@sA, lo@sA+PLANE, B@sB.
// ---------------------------------------------------------------------------
__device__ __forceinline__ void mma_chunk(uint32_t sA, uint32_t sB,
                                          float acc[4][4][4],
                                          int wm, int wn, int lane)
{
    const int aRow = (lane & 7) + ((lane >> 3) & 1) * 8;
    const int aCol = ((lane >> 4) & 1) * 8;
    const int bRow = (lane & 7) + ((lane >> 4) & 1) * 8;
    const int bCol = ((lane >> 3) & 1) * 8;

#pragma unroll
    for (int ks = 0; ks < 4; ks++) {
        uint32_t Ah[4][4], Al[4][4], Bh[2][4];
#pragma unroll
        for (int mf = 0; mf < 4; mf++) {
            uint32_t ad = sA + (uint32_t)((wm * 64 + mf * 16 + aRow) * STRIDE
                                          + ks * 16 + aCol) * 2;
            ldsm4(Ah[mf][0], Ah[mf][1], Ah[mf][2], Ah[mf][3], ad);
            ldsm4(Al[mf][0], Al[mf][1], Al[mf][2], Al[mf][3], ad + PLANE);
        }
#pragma unroll
        for (int np = 0; np < 2; np++) {
            uint32_t bd = sB + (uint32_t)((wn * 32 + np * 16 + bRow) * STRIDE
                                          + ks * 16 + bCol) * 2;
            ldsm4(Bh[np][0], Bh[np][1], Bh[np][2], Bh[np][3], bd);
        }
#pragma unroll
        for (int mf = 0; mf < 4; mf++)
#pragma unroll
            for (int nf = 0; nf < 4; nf++) {
                const uint32_t* bh = &Bh[nf >> 1][(nf & 1) * 2];
                hmma(acc[mf][nf], Ah[mf], bh);
                hmma(acc[mf][nf], Al[mf], bh);
            }
    }
}

// ---------------------------------------------------------------------------
// Kernel 0: W^T fp16, coalesced both ways via SMEM tile transpose.
// grid (32 k-tiles, 4 n-tiles, 3 z), 256 threads (32x8).
// ---------------------------------------------------------------------------
__global__ __launch_bounds__(256) void prep_w(const float* __restrict__ Wq,
                                              const float* __restrict__ Wk,
                                              const float* __restrict__ Wv)
{
    __shared__ float t[32][33];
    const int z = blockIdx.z;
    const float* W = (z == 0) ? Wq : (z == 1) ? Wk : Wv;
    const int k0 = blockIdx.x * 32, n0 = blockIdx.y * 32;
    const int tx = threadIdx.x & 31, ty = threadIdx.x >> 5;

#pragma unroll
    for (int i = 0; i < 4; i++)
        t[ty + i * 8][tx] = W[(size_t)(k0 + ty + i * 8) * Hh + n0 + tx];
    __syncthreads();
#pragma unroll
    for (int i = 0; i < 4; i++)
        g_Wt[z * Hh * Ee + (size_t)(n0 + ty + i * 8) * Ee + k0 + tx] =
            __float2half(t[tx][ty + i * 8]);
}

// ---------------------------------------------------------------------------
// Kernel 1: QKV projection, software-pipelined.
// SMEM: A hi@0, A lo@PLANE, W buf0@2*PLANE, W buf1@3*PLANE.
// ---------------------------------------------------------------------------
__global__ __launch_bounds__(256) void qkv_hmma(const float* __restrict__ x)
{
    extern __shared__ char smc[];
    const int z  = blockIdx.x;
    const int m0 = blockIdx.y * 128;
    const int tid = threadIdx.x, lane = tid & 31, wid = tid >> 5;
    const int wm = wid >> 2, wn = wid & 3;
    const uint32_t sA = smem_u32(smc);

    const __half* wh = g_Wt + z * Hh * Ee;

    // per-thread load geometry
    const int xr_r  = tid >> 1;            // x: 2 float4 per thread? no: 8 iters
    (void)xr_r;

    float acc[4][4][4] = {};
    float4 xr[8];

    // prologue: x chunk 0 -> regs, W chunk 0 -> wbuf0 via cp.async
#pragma unroll
    for (int i = 0; i < 8; i++) {
        int id = tid + i * 256;
        int r = id >> 4, ch = id & 15;
        xr[i] = *(const float4*)(x + (size_t)(m0 + r) * Ee + 0 + ch * 4);
    }
#pragma unroll
    for (int i = 0; i < 4; i++) {
        int id = tid + i * 256;
        int n = id >> 3, ch = id & 7;
        cpa16(sA + 2 * PLANE + (uint32_t)(n * STRIDE + ch * 8) * 2,
              wh + (size_t)n * Ee + 0 + ch * 8);
    }
    CPA_COMMIT();

    for (int c = 0; c < 16; c++) {
        const int cur = c & 1;
        __syncthreads();   // previous mma done reading A / this W buffer
        // store x regs -> A smem (convert to fp16 hi/lo)
#pragma unroll
        for (int i = 0; i < 8; i++) {
            int id = tid + i * 256;
            int r = id >> 4, ch = id & 15;
            float4 v = xr[i];
            __half2 h0 = __floats2half2_rn(v.x, v.y);
            __half2 h1 = __floats2half2_rn(v.z, v.w);
            __half2 l0 = __floats2half2_rn(v.x - __low2float(h0), v.y - __high2float(h0));
            __half2 l1 = __floats2half2_rn(v.z - __low2float(h1), v.w - __high2float(h1));
            char* p = smc + (r * STRIDE + ch * 4) * 2;
            *(uint2*)p           = make_uint2(*(uint32_t*)&h0, *(uint32_t*)&h1);
            *(uint2*)(p + PLANE) = make_uint2(*(uint32_t*)&l0, *(uint32_t*)&l1);
        }
        if (c < 15) {
            const int k1 = (c + 1) * 64;
            // prefetch next x chunk into regs (consumed next iter; hides under mma)
#pragma unroll
            for (int i = 0; i < 8; i++) {
                int id = tid + i * 256;
                int r = id >> 4, ch = id & 15;
                xr[i] = *(const float4*)(x + (size_t)(m0 + r) * Ee + k1 + ch * 4);
            }
            // prefetch next W chunk into the other buffer
#pragma unroll
            for (int i = 0; i < 4; i++) {
                int id = tid + i * 256;
                int n = id >> 3, ch = id & 7;
                cpa16(sA + (2 + (1 - cur)) * PLANE + (uint32_t)(n * STRIDE + ch * 8) * 2,
                      wh + (size_t)n * Ee + k1 + ch * 8);
            }
            CPA_COMMIT();
            CPA_WAIT1();   // current chunk's W arrived
        } else {
            CPA_WAIT0();
        }
        __syncthreads();
        mma_chunk(sA, sA + (2 + cur) * PLANE, acc, wm, wn, lane);
    }

    const int gid = lane >> 2, tig = lane & 3;
    if (z == 0) {
#pragma unroll
        for (int mf = 0; mf < 4; mf++)
#pragma unroll
            for (int nf = 0; nf < 4; nf++) {
                int col = wn * 32 + nf * 8 + tig * 2;
                int r0  = m0 + wm * 64 + mf * 16 + gid;
                uint32_t h, l;
                pack_hilo(h, l, acc[mf][nf][0], acc[mf][nf][1]);
                *(uint32_t*)&g_Qhi[(size_t)r0 * Hh + col] = h;
                *(uint32_t*)&g_Qlo[(size_t)r0 * Hh + col] = l;
                pack_hilo(h, l, acc[mf][nf][2], acc[mf][nf][3]);
                *(uint32_t*)&g_Qhi[(size_t)(r0 + 8) * Hh + col] = h;
                *(uint32_t*)&g_Qlo[(size_t)(r0 + 8) * Hh + col] = l;
            }
    } else if (z == 1) {
#pragma unroll
        for (int mf = 0; mf < 4; mf++)
#pragma unroll
            for (int nf = 0; nf < 4; nf++) {
                int col = wn * 32 + nf * 8 + tig * 2;
                int r0  = m0 + wm * 64 + mf * 16 + gid;
                *(__half2*)&g_K[(size_t)r0 * Hh + col] =
                    __floats2half2_rn(acc[mf][nf][0], acc[mf][nf][1]);
                *(__half2*)&g_K[(size_t)(r0 + 8) * Hh + col] =
                    __floats2half2_rn(acc[mf][nf][2], acc[mf][nf][3]);
            }
    } else {
#pragma unroll
        for (int mf = 0; mf < 4; mf++)
#pragma unroll
            for (int nf = 0; nf < 4; nf++) {
                int n  = wn * 32 + nf * 8 + tig * 2;
                int r0 = m0 + wm * 64 + mf * 16 + gid;
                g_Vt[(size_t)n * MTOT + r0]           = __float2half(acc[mf][nf][0]);
                g_Vt[(size_t)(n + 1) * MTOT + r0]     = __float2half(acc[mf][nf][1]);
                g_Vt[(size_t)n * MTOT + r0 + 8]       = __float2half(acc[mf][nf][2]);
                g_Vt[(size_t)(n + 1) * MTOT + r0 + 8] = __float2half(acc[mf][nf][3]);
            }
    }
}

// ---------------------------------------------------------------------------
// Kernel 2: split-K flash attention, cp.async double-buffered K/V.
// SMEM: Q hi@0, Q lo@FPL, buf0 K@2FPL V@3FPL, buf1 K@4FPL V@5FPL. (209 KB)
// ---------------------------------------------------------------------------
__global__ __launch_bounds__(256) void attn_split()
{
    const int gi = blockIdx.x;
    const int it = gi >> 3;
    const int b  = gi & 7;
    const int qt = WK_QT[it];
    const int c0 = WK_C0[it];
    const int nk = WK_NK[it];
    const int klast = c0 + nk - 1;

    extern __shared__ char smc[];
    const int tid = threadIdx.x, lane = tid & 31, wid = tid >> 5;
    const int gid = lane >> 2, tig = lane & 3;

    const uint32_t sQ = smem_u32(smc);

    // prologue: Q (hi/lo) + first K/V tile into buf0, one cp.async group
    {
        const int qb = b * Tt + qt * 128;
        const int kb = b * Tt + c0 * 128;
#pragma unroll
        for (int i = 0; i < 8; i++) {
            int id = tid + i * 256;
            int r = id >> 4, col = (id & 15) * 8;
            uint32_t off = (uint32_t)(r * FSTR + col) * 2;
            cpa16(sQ + off,           g_Qhi + (size_t)(qb + r) * Hh + col);
            cpa16(sQ + FPL + off,     g_Qlo + (size_t)(qb + r) * Hh + col);
            cpa16(sQ + 2 * FPL + off, g_K   + (size_t)(kb + r) * Hh + col);
            cpa16(sQ + 3 * FPL + off, g_Vt  + (size_t)r * MTOT + kb + col);
        }
        CPA_COMMIT();
    }

    float Oa[16][4] = {};
    float m0 = -INFINITY, m1 = -INFINITY, l0 = 0.f, l1 = 0.f;

    const int aRow = (lane & 7) + ((lane >> 3) & 1) * 8;
    const int aCol = ((lane >> 4) & 1) * 8;
    const int bRow = (lane & 7) + ((lane >> 4) & 1) * 8;
    const int bCol = ((lane >> 3) & 1) * 8;

    const int r0w = wid * 16 + gid;

    for (int kt = c0; kt <= klast; kt++) {
        const int cur = (kt - c0) & 1;
        if (kt < klast) {
            // prefetch next tile into the other buffer
            const int kb2 = b * Tt + (kt + 1) * 128;
            const uint32_t bb = sQ + (2 + 2 * (1 - cur)) * FPL;
#pragma unroll
            for (int i = 0; i < 8; i++) {
                int id = tid + i * 256;
                int r = id >> 4, col = (id & 15) * 8;
                uint32_t off = (uint32_t)(r * FSTR + col) * 2;
                cpa16(bb + off,       g_K  + (size_t)(kb2 + r) * Hh + col);
                cpa16(bb + FPL + off, g_Vt + (size_t)r * MTOT + kb2 + col);
            }
            CPA_COMMIT();
            CPA_WAIT1();   // current tile (and Q) arrived
        } else {
            CPA_WAIT0();
        }
        __syncthreads();

        const uint32_t sK = sQ + (2 + 2 * cur) * FPL;
        const uint32_t sV = sK + FPL;

        // ---- S = Q K^T (2-term fp16) ----
        float Sa[16][4] = {};
#pragma unroll
        for (int kc = 0; kc < 8; kc++) {
            uint32_t Ah[4], Al[4];
            uint32_t ad = sQ + (uint32_t)((wid * 16 + aRow) * FSTR + kc * 16 + aCol) * 2;
            ldsm4(Ah[0], Ah[1], Ah[2], Ah[3], ad);
            ldsm4(Al[0], Al[1], Al[2], Al[3], ad + FPL);
#pragma unroll
            for (int ng = 0; ng < 8; ng++) {
                uint32_t Bh[4];
                uint32_t bd = sK + (uint32_t)((ng * 16 + bRow) * FSTR + kc * 16 + bCol) * 2;
                ldsm4(Bh[0], Bh[1], Bh[2], Bh[3], bd);
#pragma unroll
                for (int j = 0; j < 2; j++) {
                    hmma(Sa[ng * 2 + j], Ah, &Bh[2 * j]);
                    hmma(Sa[ng * 2 + j], Al, &Bh[2 * j]);
                }
            }
        }

        // ---- scale + causal mask + online softmax ----
        const bool diag = (kt == qt);
        float bm0 = -INFINITY, bm1 = -INFINITY;
#pragma unroll
        for (int nf = 0; nf < 16; nf++) {
            int c = nf * 8 + tig * 2;
            float v0 = Sa[nf][0] * SC2, v1 = Sa[nf][1] * SC2;
            float v2 = Sa[nf][2] * SC2, v3 = Sa[nf][3] * SC2;
            if (diag) {
                if (c     > r0w)     v0 = -INFINITY;
                if (c + 1 > r0w)     v1 = -INFINITY;
                if (c     > r0w + 8) v2 = -INFINITY;
                if (c + 1 > r0w + 8) v3 = -INFINITY;
            }
            Sa[nf][0] = v0; Sa[nf][1] = v1; Sa[nf][2] = v2; Sa[nf][3] = v3;
            bm0 = fmaxf(bm0, fmaxf(v0, v1));
            bm1 = fmaxf(bm1, fmaxf(v2, v3));
        }
        bm0 = fmaxf(bm0, __shfl_xor_sync(0xFFFFFFFFu, bm0, 1));
        bm0 = fmaxf(bm0, __shfl_xor_sync(0xFFFFFFFFu, bm0, 2));
        bm1 = fmaxf(bm1, __shfl_xor_sync(0xFFFFFFFFu, bm1, 1));
        bm1 = fmaxf(bm1, __shfl_xor_sync(0xFFFFFFFFu, bm1, 2));

        float nm0 = fmaxf(m0, bm0), nm1 = fmaxf(m1, bm1);
        float a0 = exp2f(m0 - nm0), a1 = exp2f(m1 - nm1);
        m0 = nm0; m1 = nm1;

        float s0 = 0.f, s1 = 0.f;
#pragma unroll
        for (int nf = 0; nf < 16; nf++) {
            Sa[nf][0] = exp2f(Sa[nf][0] - nm0);
            Sa[nf][1] = exp2f(Sa[nf][1] - nm0);
            Sa[nf][2] = exp2f(Sa[nf][2] - nm1);
            Sa[nf][3] = exp2f(Sa[nf][3] - nm1);
            s0 += Sa[nf][0] + Sa[nf][1];
            s1 += Sa[nf][2] + Sa[nf][3];
        }
        s0 += __shfl_xor_sync(0xFFFFFFFFu, s0, 1);
        s0 += __shfl_xor_sync(0xFFFFFFFFu, s0, 2);
        s1 += __shfl_xor_sync(0xFFFFFFFFu, s1, 1);
        s1 += __shfl_xor_sync(0xFFFFFFFFu, s1, 2);
        l0 = l0 * a0 + s0;
        l1 = l1 * a1 + s1;

#pragma unroll
        for (int nf = 0; nf < 16; nf++) {
            Oa[nf][0] *= a0; Oa[nf][1] *= a0;
            Oa[nf][2] *= a1; Oa[nf][3] *= a1;
        }

        // ---- O += P V (2-term fp16) ----
#pragma unroll
        for (int kc = 0; kc < 8; kc++) {
            uint32_t Ph[4], Pl[4];
            pack_hilo(Ph[0], Pl[0], Sa[2 * kc][0],     Sa[2 * kc][1]);
            pack_hilo(Ph[1], Pl[1], Sa[2 * kc][2],     Sa[2 * kc][3]);
            pack_hilo(Ph[2], Pl[2], Sa[2 * kc + 1][0], Sa[2 * kc + 1][1]);
            pack_hilo(Ph[3], Pl[3], Sa[2 * kc + 1][2], Sa[2 * kc + 1][3]);
#pragma unroll
            for (int ng = 0; ng < 8; ng++) {
                uint32_t Vh[4];
                uint32_t bd = sV + (uint32_t)((ng * 16 + bRow) * FSTR + kc * 16 + bCol) * 2;
                ldsm4(Vh[0], Vh[1], Vh[2], Vh[3], bd);
#pragma unroll
                for (int j = 0; j < 2; j++) {
                    hmma(Oa[ng * 2 + j], Ph, &Vh[2 * j]);
                    hmma(Oa[ng * 2 + j], Pl, &Vh[2 * j]);
                }
            }
        }
        __syncthreads();   // all warps done with buf[cur] before it is refilled
    }

    // ---- epilogue: unnormalized partial + per-row m, l ----
    float* Op = g_Opart[gi];
#pragma unroll
    for (int nf = 0; nf < 16; nf++) {
        int col = nf * 8 + tig * 2;
        *(float2*)&Op[r0w * 128 + col]       = make_float2(Oa[nf][0], Oa[nf][1]);
        *(float2*)&Op[(r0w + 8) * 128 + col] = make_float2(Oa[nf][2], Oa[nf][3]);
    }
    if (tig == 0) {
        g_mpart[gi][r0w]     = m0;
        g_lpart[gi][r0w]     = l0;
        g_mpart[gi][r0w + 8] = m1;
        g_lpart[gi][r0w + 8] = l1;
    }
}

// ---------------------------------------------------------------------------
// Kernel 3: merge partials.  grid (16 qt, 8 b, 8 row-groups), 256 threads.
// Thread = (row within 16-row group, 8-col chunk).
// ---------------------------------------------------------------------------
__global__ __launch_bounds__(256) void attn_merge(float* __restrict__ out)
{
    const int qt = blockIdx.x, b = blockIdx.y, rg = blockIdx.z;
    const int nch = QT_NCH[qt];

    const int tid = threadIdx.x;
    const int r   = rg * 16 + (tid >> 4);
    const int co  = (tid & 15) * 8;

    int gi[4];
    float mv[4];
    float mmax = -INFINITY;
#pragma unroll
    for (int j = 0; j < 4; j++) {
        if (j < nch) {
            gi[j] = QT_ITEMS[qt][j] * 8 + b;
            mv[j] = g_mpart[gi[j]][r];
            mmax  = fmaxf(mmax, mv[j]);
        }
    }
    float a[4];
    float lsum = 0.f;
#pragma unroll
    for (int j = 0; j < 4; j++) {
        if (j < nch) {
            a[j] = exp2f(mv[j] - mmax);
            lsum += a[j] * g_lpart[gi[j]][r];
        }
    }
    const float inv = 1.f / lsum;

    float* orow = out + ((size_t)(b * Tt + qt * 128 + r)) * Hh + co;
#pragma unroll
    for (int c = 0; c < 2; c++) {
        float4 acc = make_float4(0.f, 0.f, 0.f, 0.f);
#pragma unroll
        for (int j = 0; j < 4; j++) {
            if (j < nch) {
                float4 v = *(const float4*)&g_Opart[gi[j]][r * 128 + co + c * 4];
                acc.x += a[j] * v.x;
                acc.y += a[j] * v.y;
                acc.z += a[j] * v.z;
                acc.w += a[j] * v.w;
            }
        }
        acc.x *= inv; acc.y *= inv; acc.z *= inv; acc.w *= inv;
        *(float4*)&orow[c * 4] = acc;
    }
}

// ---------------------------------------------------------------------------
extern "C" void kernel_launch(void* const* d_in, const int* in_sizes, int n_in,
                              void* d_out, int out_size)
{
    const float* x  = (const float*)d_in[0];
    const float* Wq = (const float*)d_in[1];
    const float* Wk = (const float*)d_in[2];
    const float* Wv = (const float*)d_in[3];
    float* out = (float*)d_out;

    const int SMEM_QKV  = 4 * PLANE;   // 73728
    const int SMEM_ATTN = 6 * FPL;     // 208896
    cudaFuncSetAttribute(qkv_hmma,   cudaFuncAttributeMaxDynamicSharedMemorySize, SMEM_QKV);
    cudaFuncSetAttribute(attn_split, cudaFuncAttributeMaxDynamicSharedMemorySize, SMEM_ATTN);

    prep_w<<<dim3(32, 4, 3), 256>>>(Wq, Wk, Wv);
    qkv_hmma<<<dim3(3, 128), 256, SMEM_QKV>>>(x);
    attn_split<<<NCTA, 256, SMEM_ATTN>>>();
    attn_merge<<<dim3(16, 8, 8), 256>>>(out);
}